// round 4
// baseline (speedup 1.0000x reference)
#include <cuda_runtime.h>
#include <cuda_bf16.h>

// Problem constants
#define KCODES 1024
#define DDIM   256
#define NROWS  65536
#define DECAYF 0.99f
#define ONE_MINUS_DECAY 0.01f
#define BETAF  0.25f
#define EPSF   1e-5f
#define GAP_THRESH 1.25e-4f   // ~4 ulp of dist (~257); flags rows for exact refinement

// Scratch (__device__ globals; no allocations allowed)
__device__ float  g_esq[KCODES];              // ||e_k||^2 (exactly rounded)
__device__ float  g_zsq[NROWS];               // ||z_row||^2 (exactly rounded)
__device__ int    g_codes[NROWS];
__device__ float  g_bestv[NROWS];
__device__ float  g_secondv[NROWS];
__device__ float  g_cs_batch[KCODES];
__device__ float  g_embed_sum[KCODES * DDIM];
__device__ double g_loss;
__device__ float  g_nsum;

// ---------------------------------------------------------------------------
// Kernel 0e: ||e_k||^2 in double -> float; zero scatter buffers + loss
// grid: KCODES blocks x DDIM threads
// ---------------------------------------------------------------------------
__global__ __launch_bounds__(DDIM) void k0_esq(const float* __restrict__ emb) {
    __shared__ double red[DDIM];
    int k = blockIdx.x;
    int t = threadIdx.x;
    float v = emb[(size_t)k * DDIM + t];
    red[t] = (double)v * (double)v;
    g_embed_sum[(size_t)k * DDIM + t] = 0.0f;
    __syncthreads();
    for (int s = DDIM / 2; s > 0; s >>= 1) {
        if (t < s) red[t] += red[t + s];
        __syncthreads();
    }
    if (t == 0) {
        g_esq[k] = (float)red[0];
        g_cs_batch[k] = 0.0f;
        if (k == 0) { g_loss = 0.0; g_nsum = 0.0f; }
    }
}

// ---------------------------------------------------------------------------
// Kernel 0z: ||z_row||^2 in double -> float. One warp per row.
// grid: NROWS/8 blocks x 256 threads
// ---------------------------------------------------------------------------
__global__ __launch_bounds__(256) void k0_zsq(const float* __restrict__ z) {
    int warp = threadIdx.x >> 5;
    int lane = threadIdx.x & 31;
    int row  = blockIdx.x * 8 + warp;
    const float4* p = (const float4*)(z + (size_t)row * DDIM);
    double s = 0.0;
#pragma unroll
    for (int i = 0; i < 2; i++) {
        float4 v = p[lane + i * 32];
        s += (double)v.x * v.x + (double)v.y * v.y + (double)v.z * v.z + (double)v.w * v.w;
    }
#pragma unroll
    for (int off = 16; off > 0; off >>= 1)
        s += __shfl_down_sync(0xffffffffu, s, off);
    if (lane == 0) g_zsq[row] = (float)s;
}

// ---------------------------------------------------------------------------
// Kernel 1: SGEMM dot = z.e, epilogue v = RN(RN(z_sq - 2*dot) + e_sq),
// argmin over k with lowest-index tie-break; track second-best for refinement.
// 128x128 tile, TKD=32 depth, 256 threads, 8x8 per thread.
// ---------------------------------------------------------------------------
#define TM 128
#define TN 128
#define TKD 32

__global__ __launch_bounds__(256) void k1_argmin(const float* __restrict__ z,
                                                 const float* __restrict__ emb,
                                                 int* __restrict__ codes_i,
                                                 float* __restrict__ codes_f) {
    __shared__ float zs[TKD][TM + 4];
    __shared__ float es[TKD][TN + 4];

    const int t  = threadIdx.x;
    const int tr = t >> 4;   // 0..15 row group
    const int tc = t & 15;   // 0..15 col group
    const int row0 = blockIdx.x * TM;

    float best[8], secv[8];
    int   bidx[8];
#pragma unroll
    for (int i = 0; i < 8; i++) { best[i] = 3.0e38f; secv[i] = 3.0e38f; bidx[i] = 0x7fffffff; }

    float zsq[8];
#pragma unroll
    for (int i = 0; i < 8; i++) zsq[i] = g_zsq[row0 + tr * 8 + i];

    for (int n0 = 0; n0 < KCODES; n0 += TN) {
        float acc[8][8];
#pragma unroll
        for (int i = 0; i < 8; i++)
#pragma unroll
            for (int j = 0; j < 8; j++) acc[i][j] = 0.0f;

        for (int k0 = 0; k0 < DDIM; k0 += TKD) {
#pragma unroll
            for (int i = 0; i < 4; i++) {
                int fid = t + i * 256;
                int r   = fid >> 3;
                int cf  = fid & 7;
                float4 v = *(const float4*)(z + (size_t)(row0 + r) * DDIM + k0 + cf * 4);
                zs[cf * 4 + 0][r] = v.x;
                zs[cf * 4 + 1][r] = v.y;
                zs[cf * 4 + 2][r] = v.z;
                zs[cf * 4 + 3][r] = v.w;
                float4 w = *(const float4*)(emb + (size_t)(n0 + r) * DDIM + k0 + cf * 4);
                es[cf * 4 + 0][r] = w.x;
                es[cf * 4 + 1][r] = w.y;
                es[cf * 4 + 2][r] = w.z;
                es[cf * 4 + 3][r] = w.w;
            }
            __syncthreads();

#pragma unroll 4
            for (int k = 0; k < TKD; k++) {
                float zv[8], ev[8];
                *(float4*)&zv[0] = *(const float4*)&zs[k][tr * 8];
                *(float4*)&zv[4] = *(const float4*)&zs[k][tr * 8 + 4];
                *(float4*)&ev[0] = *(const float4*)&es[k][tc * 8];
                *(float4*)&ev[4] = *(const float4*)&es[k][tc * 8 + 4];
#pragma unroll
                for (int i = 0; i < 8; i++)
#pragma unroll
                    for (int j = 0; j < 8; j++)
                        acc[i][j] += zv[i] * ev[j];
            }
            __syncthreads();
        }

        // Epilogue for this code tile: quantized-formula distance + argmin fold
#pragma unroll
        for (int j = 0; j < 8; j++) {
            int col = n0 + tc * 8 + j;
            float esq = g_esq[col];
#pragma unroll
            for (int i = 0; i < 8; i++) {
                // replicate RN(RN(z_sq - 2*dot) + e_sq); 2*dot is exact
                float u = __fadd_rn(zsq[i], -2.0f * acc[i][j]);
                float v = __fadd_rn(u, esq);
                if (v < best[i]) { secv[i] = best[i]; best[i] = v; bidx[i] = col; }
                else if (v < secv[i]) { secv[i] = v; }
            }
        }
    }

    // Cross-thread (16 tc groups) reduction per row; alias smem
    __syncthreads();
    float* rv = &zs[0][0];                 // [128][16] best values
    float* rs = &zs[0][0] + 2048;          // [128][16] second values
    int*   ri = (int*)&es[0][0];           // [128][16] best indices
#pragma unroll
    for (int i = 0; i < 8; i++) {
        int row = tr * 8 + i;
        rv[row * 16 + tc] = best[i];
        rs[row * 16 + tc] = secv[i];
        ri[row * 16 + tc] = bidx[i];
    }
    __syncthreads();
    if (t < TM) {
        float bv = 3.0e38f, sv2 = 3.0e38f;
        int   bi = 0x7fffffff;
#pragma unroll
        for (int c = 0; c < 16; c++) {
            float v  = rv[t * 16 + c];
            float s2 = rs[t * 16 + c];
            int   id = ri[t * 16 + c];
            if (v < bv || (v == bv && id < bi)) {
                sv2 = fminf(sv2, fminf(bv, s2));
                bv = v; bi = id;
            } else {
                sv2 = fminf(sv2, fminf(v, s2));
            }
        }
        int row = row0 + t;
        g_bestv[row]   = bv;
        g_secondv[row] = sv2;
        codes_i[row] = bi;
        codes_f[row] = (float)bi;
    }
}

// ---------------------------------------------------------------------------
// Kernel 1r: exact refinement for rows with quantized gap <= GAP_THRESH.
// fp64 dot -> exactly rounded fp32 -> same quantized formula -> argmin with
// lowest-index tie-break. One block (256 thr) per row; early exit otherwise.
// ---------------------------------------------------------------------------
__global__ __launch_bounds__(256) void k1_refine(const float* __restrict__ z,
                                                 const float* __restrict__ emb,
                                                 int* __restrict__ codes_i,
                                                 float* __restrict__ codes_f) {
    int row = blockIdx.x;
    if (g_secondv[row] - g_bestv[row] > GAP_THRESH) return;

    __shared__ float zrow[DDIM];
    __shared__ float sv[256];
    __shared__ int   si[256];
    int t = threadIdx.x;
    zrow[t] = z[(size_t)row * DDIM + t];
    __syncthreads();

    float zsq = g_zsq[row];
    float bv = 3.0e38f;
    int   bi = 0x7fffffff;
    for (int c = t; c < KCODES; c += 256) {
        const float4* e4 = (const float4*)(emb + (size_t)c * DDIM);
        const float4* z4 = (const float4*)zrow;
        double dot = 0.0;
#pragma unroll 8
        for (int q = 0; q < DDIM / 4; q++) {
            float4 ev = e4[q];
            float4 zv = z4[q];
            dot += (double)zv.x * ev.x + (double)zv.y * ev.y
                 + (double)zv.z * ev.z + (double)zv.w * ev.w;
        }
        float m = (float)(2.0 * dot);           // exactly rounded RN(2*dot)
        float u = __fadd_rn(zsq, -m);
        float v = __fadd_rn(u, g_esq[c]);
        if (v < bv) { bv = v; bi = c; }         // ascending c keeps lowest index
    }
    sv[t] = bv; si[t] = bi;
    __syncthreads();
    for (int s = 128; s > 0; s >>= 1) {
        if (t < s) {
            float v = sv[t + s]; int id = si[t + s];
            if (v < sv[t] || (v == sv[t] && id < si[t])) { sv[t] = v; si[t] = id; }
        }
        __syncthreads();
    }
    if (t == 0) {
        codes_i[row] = si[0];
        codes_f[row] = (float)si[0];
    }
}

// ---------------------------------------------------------------------------
// Kernel 2: gather z_q, commit-loss partials, scatter embed_sum / counts
// ---------------------------------------------------------------------------
__global__ __launch_bounds__(DDIM) void k2_gather_scatter(const float* __restrict__ z,
                                                          const float* __restrict__ emb,
                                                          const int* __restrict__ codes,
                                                          float* __restrict__ zq_out) {
    __shared__ float red[DDIM];
    const int t = threadIdx.x;
    const int row0 = blockIdx.x * 8;
    float lsum = 0.0f;
#pragma unroll
    for (int r = 0; r < 8; r++) {
        int row = row0 + r;
        int c = codes[row];
        float zv = z[(size_t)row * DDIM + t];
        float ev = emb[(size_t)c * DDIM + t];
        zq_out[(size_t)row * DDIM + t] = ev;    // straight-through fwd == z_q
        float d = zv - ev;
        lsum += d * d;
        atomicAdd(&g_embed_sum[(size_t)c * DDIM + t], zv);
        if (t == 0) atomicAdd(&g_cs_batch[c], 1.0f);
    }
    red[t] = lsum;
    __syncthreads();
    for (int s = DDIM / 2; s > 0; s >>= 1) {
        if (t < s) red[t] += red[t + s];
        __syncthreads();
    }
    if (t == 0) atomicAdd(&g_loss, (double)red[0]);
}

// ---------------------------------------------------------------------------
// Kernel 3: new_cluster_size + n-sum + vq_loss (single block, KCODES threads)
// ---------------------------------------------------------------------------
__global__ __launch_bounds__(KCODES) void k3_cluster(const float* __restrict__ cs_in,
                                                     float* __restrict__ cs_out,
                                                     float* __restrict__ loss_out,
                                                     float inv_nd) {
    __shared__ float red[KCODES];
    int t = threadIdx.x;
    float ncs = cs_in[t] * DECAYF + g_cs_batch[t] * ONE_MINUS_DECAY;
    cs_out[t] = ncs;
    red[t] = ncs;
    __syncthreads();
    for (int s = KCODES / 2; s > 0; s >>= 1) {
        if (t < s) red[t] += red[t + s];
        __syncthreads();
    }
    if (t == 0) {
        g_nsum = red[0];
        loss_out[0] = BETAF * (float)(g_loss * (double)inv_nd);
    }
}

// ---------------------------------------------------------------------------
// Kernel 4: new_embed_avg + smoothed normalize -> new_embedding
// ---------------------------------------------------------------------------
__global__ __launch_bounds__(DDIM) void k4_embed(const float* __restrict__ avg_in,
                                                 const float* __restrict__ cs_out,
                                                 float* __restrict__ avg_out,
                                                 float* __restrict__ emb_out) {
    int k = blockIdx.x;
    int t = threadIdx.x;
    size_t idx = (size_t)k * DDIM + t;
    float na = avg_in[idx] * DECAYF + g_embed_sum[idx] * ONE_MINUS_DECAY;
    avg_out[idx] = na;
    float n = g_nsum;
    float css = (cs_out[k] + EPSF) / (n + (float)KCODES * EPSF) * n;
    emb_out[idx] = na / css;
}

// ---------------------------------------------------------------------------
extern "C" void kernel_launch(void* const* d_in, const int* in_sizes, int n_in,
                              void* d_out, int out_size) {
    const float* z_e  = (const float*)d_in[0];  // [N, D]
    const float* emb  = (const float*)d_in[1];  // [K, D]
    const float* cs   = (const float*)d_in[2];  // [K]
    const float* eavg = (const float*)d_in[3];  // [K, D]

    const int n_ze = in_sizes[0];               // N*D
    const int KD   = in_sizes[1];               // K*D
    const int Kk   = in_sizes[2];               // K
    const int D    = KD / Kk;
    const int N    = n_ze / D;

    float* out = (float*)d_out;
    // Tuple order: z_q_st, vq_loss, codes, new_embedding, new_cluster_size, new_embed_avg
    float* o_zq    = out;
    float* o_loss  = out + (size_t)n_ze;
    float* o_codes = o_loss + 1;
    float* o_emb   = o_codes + N;
    float* o_cs    = o_emb + KD;
    float* o_avg   = o_cs + Kk;

    int* codes_dev;
    cudaGetSymbolAddress((void**)&codes_dev, g_codes);

    k0_esq<<<Kk, D>>>(emb);
    k0_zsq<<<N / 8, 256>>>(z_e);
    k1_argmin<<<N / TM, 256>>>(z_e, emb, codes_dev, o_codes);
    k1_refine<<<N, 256>>>(z_e, emb, codes_dev, o_codes);
    k2_gather_scatter<<<N / 8, D>>>(z_e, emb, codes_dev, o_zq);
    k3_cluster<<<1, Kk>>>(cs, o_cs, o_loss, 1.0f / (float)n_ze);
    k4_embed<<<Kk, D>>>(eavg, o_cs, o_avg, o_emb);
}

// round 5
// speedup vs baseline: 1.5499x; 1.5499x over previous
#include <cuda_runtime.h>
#include <cuda_bf16.h>
#include <stdint.h>

// Problem constants
#define KCODES 1024
#define DDIM   256
#define NROWS  65536
#define DECAYF 0.99f
#define ONE_MINUS_DECAY 0.01f
#define BETAF  0.25f
#define EPSF   1e-5f
#define GAPF   2e-3f      // flag threshold: covers max bf16-split dot error (~8e-4) w/ margin

// Scratch (__device__ globals; no allocations allowed)
__device__ __align__(16) __nv_bfloat16 g_zh[NROWS * DDIM];
__device__ __align__(16) __nv_bfloat16 g_zl[NROWS * DDIM];
__device__ __align__(16) __nv_bfloat16 g_eh[KCODES * DDIM];
__device__ __align__(16) __nv_bfloat16 g_el[KCODES * DDIM];
__device__ float  g_esq[KCODES];
__device__ float  g_zsq[NROWS];
__device__ int    g_codes[NROWS];
__device__ float  g_bestv[NROWS];
__device__ float  g_secondv[NROWS];
__device__ int    g_flag_list[NROWS];
__device__ int    g_flag_cnt;
__device__ float  g_cs_batch[KCODES];
__device__ float  g_embed_sum[KCODES * DDIM];
__device__ double g_loss;
__device__ float  g_nsum;

// ---------------------------------------------------------------------------
// Split fp32 -> bf16 hi + bf16 lo (residual). 4 floats per thread.
// ---------------------------------------------------------------------------
__global__ __launch_bounds__(256) void k_split(const float* __restrict__ src,
                                               __nv_bfloat16* __restrict__ h,
                                               __nv_bfloat16* __restrict__ l) {
    int idx = blockIdx.x * 256 + threadIdx.x;      // float4 index
    float4 v = ((const float4*)src)[idx];
    __nv_bfloat16 h0 = __float2bfloat16_rn(v.x);
    __nv_bfloat16 h1 = __float2bfloat16_rn(v.y);
    __nv_bfloat16 h2 = __float2bfloat16_rn(v.z);
    __nv_bfloat16 h3 = __float2bfloat16_rn(v.w);
    __nv_bfloat16 l0 = __float2bfloat16_rn(v.x - __bfloat162float(h0));
    __nv_bfloat16 l1 = __float2bfloat16_rn(v.y - __bfloat162float(h1));
    __nv_bfloat16 l2 = __float2bfloat16_rn(v.z - __bfloat162float(h2));
    __nv_bfloat16 l3 = __float2bfloat16_rn(v.w - __bfloat162float(h3));
    __nv_bfloat162* hp = reinterpret_cast<__nv_bfloat162*>(h) + idx * 2;
    __nv_bfloat162* lp = reinterpret_cast<__nv_bfloat162*>(l) + idx * 2;
    __nv_bfloat162 a; a.x = h0; a.y = h1; hp[0] = a;
    __nv_bfloat162 b; b.x = h2; b.y = h3; hp[1] = b;
    __nv_bfloat162 c; c.x = l0; c.y = l1; lp[0] = c;
    __nv_bfloat162 d; d.x = l2; d.y = l3; lp[1] = d;
}

// ---------------------------------------------------------------------------
// k0_esq: ||e_k||^2 in double -> float; zero scatter buffers + counters
// ---------------------------------------------------------------------------
__global__ __launch_bounds__(DDIM) void k0_esq(const float* __restrict__ emb) {
    __shared__ double red[DDIM];
    int k = blockIdx.x;
    int t = threadIdx.x;
    float v = emb[(size_t)k * DDIM + t];
    red[t] = (double)v * (double)v;
    g_embed_sum[(size_t)k * DDIM + t] = 0.0f;
    __syncthreads();
    for (int s = DDIM / 2; s > 0; s >>= 1) {
        if (t < s) red[t] += red[t + s];
        __syncthreads();
    }
    if (t == 0) {
        g_esq[k] = (float)red[0];
        g_cs_batch[k] = 0.0f;
        if (k == 0) { g_loss = 0.0; g_nsum = 0.0f; g_flag_cnt = 0; }
    }
}

// ---------------------------------------------------------------------------
// k0_zsq: ||z_row||^2 in double -> float. One warp per row.
// ---------------------------------------------------------------------------
__global__ __launch_bounds__(256) void k0_zsq(const float* __restrict__ z) {
    int warp = threadIdx.x >> 5;
    int lane = threadIdx.x & 31;
    int row  = blockIdx.x * 8 + warp;
    const float4* p = (const float4*)(z + (size_t)row * DDIM);
    double s = 0.0;
#pragma unroll
    for (int i = 0; i < 2; i++) {
        float4 v = p[lane + i * 32];
        s += (double)v.x * v.x + (double)v.y * v.y + (double)v.z * v.z + (double)v.w * v.w;
    }
#pragma unroll
    for (int off = 16; off > 0; off >>= 1)
        s += __shfl_down_sync(0xffffffffu, s, off);
    if (lane == 0) g_zsq[row] = (float)s;
}

// ---------------------------------------------------------------------------
// mma helpers
// ---------------------------------------------------------------------------
__device__ __forceinline__ void ldsm_x4(uint32_t& r0, uint32_t& r1, uint32_t& r2, uint32_t& r3,
                                        uint32_t addr) {
    asm volatile("ldmatrix.sync.aligned.m8n8.x4.shared.b16 {%0,%1,%2,%3}, [%4];"
                 : "=r"(r0), "=r"(r1), "=r"(r2), "=r"(r3) : "r"(addr));
}
__device__ __forceinline__ void ldsm_x2(uint32_t& r0, uint32_t& r1, uint32_t addr) {
    asm volatile("ldmatrix.sync.aligned.m8n8.x2.shared.b16 {%0,%1}, [%2];"
                 : "=r"(r0), "=r"(r1) : "r"(addr));
}
__device__ __forceinline__ void mma_bf16(float* c, uint32_t a0, uint32_t a1, uint32_t a2,
                                         uint32_t a3, uint32_t b0, uint32_t b1) {
    asm volatile("mma.sync.aligned.m16n8k16.row.col.f32.bf16.bf16.f32 "
                 "{%0,%1,%2,%3}, {%4,%5,%6,%7}, {%8,%9}, {%0,%1,%2,%3};"
                 : "+f"(c[0]), "+f"(c[1]), "+f"(c[2]), "+f"(c[3])
                 : "r"(a0), "r"(a1), "r"(a2), "r"(a3), "r"(b0), "r"(b1));
}
__device__ __forceinline__ void upd(float& b, float& s, int& i, float v, int col) {
    if (v < b) { s = b; b = v; i = col; }
    else if (v < s) { s = v; }
}
__device__ __forceinline__ void merge2(float& b, float& s, int& i,
                                       float ob, float os, int oi) {
    float ns = fminf(s, os);
    if (ob < b || (ob == b && oi < i)) { ns = fminf(ns, b); b = ob; i = oi; }
    else { ns = fminf(ns, ob); }
    s = ns;
}

// ---------------------------------------------------------------------------
// Kernel 1: 3-term bf16-split GEMM (zh*eh + zl*eh + zh*el) via mma.sync,
// fused quantized-distance argmin epilogue with best/second tracking.
// Block: 128 rows x (passes of 128 codes). 256 thr = 8 warps (4 m x 2 n).
// Warp tile 32x64, k-chunk 32 in smem.
// ---------------------------------------------------------------------------
#define PITCH 40          // bf16 elems per smem row (32 data + 8 pad) -> 80B
#define PITCH_B 80

__global__ __launch_bounds__(256) void k1_mma(int* __restrict__ codes_i,
                                              float* __restrict__ codes_f) {
    __shared__ __nv_bfloat16 sAh[128 * PITCH];
    __shared__ __nv_bfloat16 sAl[128 * PITCH];
    __shared__ __nv_bfloat16 sBh[128 * PITCH];
    __shared__ __nv_bfloat16 sBl[128 * PITCH];
    __shared__ float sEsq[128];
    __shared__ float sFb[256];
    __shared__ float sFs[256];
    __shared__ int   sFi[256];

    const int tid  = threadIdx.x;
    const int lane = tid & 31;
    const int warp = tid >> 5;
    const int wm   = warp & 3;      // 0..3
    const int wn   = warp >> 2;     // 0..1
    const int row0 = blockIdx.x * 128;

    const uint32_t bAh = (uint32_t)__cvta_generic_to_shared(sAh);
    const uint32_t bAl = (uint32_t)__cvta_generic_to_shared(sAl);
    const uint32_t bBh = (uint32_t)__cvta_generic_to_shared(sBh);
    const uint32_t bBl = (uint32_t)__cvta_generic_to_shared(sBl);

    // zsq for this thread's 4 output rows
    const int rbase = wm * 32 + (lane >> 2);
    float zs[4];
#pragma unroll
    for (int r = 0; r < 4; r++) zs[r] = g_zsq[row0 + rbase + r * 8];

    float best[4], secv[4];
    int   bidx[4];
#pragma unroll
    for (int r = 0; r < 4; r++) { best[r] = 3.0e38f; secv[r] = 3.0e38f; bidx[r] = 0x7fffffff; }

    for (int n0 = 0; n0 < KCODES; n0 += 128) {
        __syncthreads();                       // protect sEsq/tiles from prev pass readers
        if (tid < 128) sEsq[tid] = g_esq[n0 + tid];

        float acc[2][8][4];
#pragma unroll
        for (int mt = 0; mt < 2; mt++)
#pragma unroll
            for (int nt = 0; nt < 8; nt++)
#pragma unroll
                for (int q = 0; q < 4; q++) acc[mt][nt][q] = 0.0f;

        for (int kc = 0; kc < 8; kc++) {
            const int k0 = kc * 32;
            __syncthreads();
#pragma unroll
            for (int it = 0; it < 2; it++) {
                int s   = tid + it * 256;      // 0..511
                int r   = s >> 2;
                int sub = s & 3;
                size_t ga = (size_t)(row0 + r) * DDIM + k0 + sub * 8;
                size_t gb = (size_t)(n0 + r)   * DDIM + k0 + sub * 8;
                int so = r * PITCH + sub * 8;
                *(uint4*)(sAh + so) = *(const uint4*)(g_zh + ga);
                *(uint4*)(sAl + so) = *(const uint4*)(g_zl + ga);
                *(uint4*)(sBh + so) = *(const uint4*)(g_eh + gb);
                *(uint4*)(sBl + so) = *(const uint4*)(g_el + gb);
            }
            __syncthreads();

#pragma unroll
            for (int ks = 0; ks < 2; ks++) {
                const uint32_t koff = ks * 32;
                // A fragments (hi & lo), 2 m-tiles
                uint32_t Ah[2][4], Al[2][4];
#pragma unroll
                for (int mt = 0; mt < 2; mt++) {
                    uint32_t off = (uint32_t)(wm * 32 + mt * 16 + (lane & 15)) * PITCH_B
                                 + koff + ((lane >> 4) & 1) * 16;
                    ldsm_x4(Ah[mt][0], Ah[mt][1], Ah[mt][2], Ah[mt][3], bAh + off);
                    ldsm_x4(Al[mt][0], Al[mt][1], Al[mt][2], Al[mt][3], bAl + off);
                }
                // B fragments (hi & lo), 8 n-tiles
                uint32_t Bh[8][2], Bl[8][2];
#pragma unroll
                for (int nt = 0; nt < 8; nt++) {
                    uint32_t off = (uint32_t)(wn * 64 + nt * 8 + (lane & 7)) * PITCH_B
                                 + koff + ((lane >> 3) & 1) * 16;
                    ldsm_x2(Bh[nt][0], Bh[nt][1], bBh + off);
                    ldsm_x2(Bl[nt][0], Bl[nt][1], bBl + off);
                }
#pragma unroll
                for (int mt = 0; mt < 2; mt++)
#pragma unroll
                    for (int nt = 0; nt < 8; nt++) {
                        mma_bf16(acc[mt][nt], Ah[mt][0], Ah[mt][1], Ah[mt][2], Ah[mt][3],
                                 Bh[nt][0], Bh[nt][1]);
                        mma_bf16(acc[mt][nt], Al[mt][0], Al[mt][1], Al[mt][2], Al[mt][3],
                                 Bh[nt][0], Bh[nt][1]);
                        mma_bf16(acc[mt][nt], Ah[mt][0], Ah[mt][1], Ah[mt][2], Ah[mt][3],
                                 Bl[nt][0], Bl[nt][1]);
                    }
            }
        }

        // Epilogue: quantized distance + top-2 fold (cols ascending per thread)
        const int qc = lane & 3;
#pragma unroll
        for (int nt = 0; nt < 8; nt++) {
#pragma unroll
            for (int cp = 0; cp < 2; cp++) {
                int cl  = wn * 64 + nt * 8 + qc * 2 + cp;
                float esq = sEsq[cl];
                int col = n0 + cl;
                float v;
                v = __fadd_rn(__fadd_rn(zs[0], -2.0f * acc[0][nt][cp]),     esq);
                upd(best[0], secv[0], bidx[0], v, col);
                v = __fadd_rn(__fadd_rn(zs[1], -2.0f * acc[0][nt][2 + cp]), esq);
                upd(best[1], secv[1], bidx[1], v, col);
                v = __fadd_rn(__fadd_rn(zs[2], -2.0f * acc[1][nt][cp]),     esq);
                upd(best[2], secv[2], bidx[2], v, col);
                v = __fadd_rn(__fadd_rn(zs[3], -2.0f * acc[1][nt][2 + cp]), esq);
                upd(best[3], secv[3], bidx[3], v, col);
            }
        }
    }

    // Quad reduction (lanes within group-of-4 share rows, hold different cols)
#pragma unroll
    for (int off = 1; off <= 2; off <<= 1) {
#pragma unroll
        for (int r = 0; r < 4; r++) {
            float ob = __shfl_xor_sync(0xffffffffu, best[r], off);
            float os = __shfl_xor_sync(0xffffffffu, secv[r], off);
            int   oi = __shfl_xor_sync(0xffffffffu, bidx[r], off);
            merge2(best[r], secv[r], bidx[r], ob, os, oi);
        }
    }
    if ((lane & 3) == 0) {
#pragma unroll
        for (int r = 0; r < 4; r++) {
            int rl = wm * 32 + (lane >> 2) + r * 8;
            sFb[rl * 2 + wn] = best[r];
            sFs[rl * 2 + wn] = secv[r];
            sFi[rl * 2 + wn] = bidx[r];
        }
    }
    __syncthreads();
    if (tid < 128) {
        float b = sFb[tid * 2], s = sFs[tid * 2];
        int   i = sFi[tid * 2];
        merge2(b, s, i, sFb[tid * 2 + 1], sFs[tid * 2 + 1], sFi[tid * 2 + 1]);
        int row = row0 + tid;
        g_bestv[row]   = b;
        g_secondv[row] = s;
        codes_i[row] = i;
        codes_f[row] = (float)i;
    }
}

// ---------------------------------------------------------------------------
// k1_flag: compact rows whose approximate top-2 gap <= GAPF
// ---------------------------------------------------------------------------
__global__ __launch_bounds__(256) void k1_flag() {
    int row = blockIdx.x * 256 + threadIdx.x;
    if (g_secondv[row] - g_bestv[row] <= GAPF) {
        int p = atomicAdd(&g_flag_cnt, 1);
        g_flag_list[p] = row;
    }
}

// ---------------------------------------------------------------------------
// k1_refine: exact fp64-dot recompute for flagged rows (fixed small grid).
// ---------------------------------------------------------------------------
__global__ __launch_bounds__(256) void k1_refine(const float* __restrict__ z,
                                                 const float* __restrict__ emb,
                                                 int* __restrict__ codes_i,
                                                 float* __restrict__ codes_f) {
    __shared__ float zrow[DDIM];
    __shared__ float sv[256];
    __shared__ int   si[256];
    int t = threadIdx.x;
    int cnt = g_flag_cnt;
    for (int fi = blockIdx.x; fi < cnt; fi += gridDim.x) {
        int row = g_flag_list[fi];
        zrow[t] = z[(size_t)row * DDIM + t];
        __syncthreads();

        float zsq = g_zsq[row];
        float bv = 3.0e38f;
        int   bi = 0x7fffffff;
        for (int c = t; c < KCODES; c += 256) {
            const float4* e4 = (const float4*)(emb + (size_t)c * DDIM);
            const float4* z4 = (const float4*)zrow;
            double dot = 0.0;
#pragma unroll 8
            for (int q = 0; q < DDIM / 4; q++) {
                float4 ev = e4[q];
                float4 zv = z4[q];
                dot += (double)zv.x * ev.x + (double)zv.y * ev.y
                     + (double)zv.z * ev.z + (double)zv.w * ev.w;
            }
            float m = (float)(2.0 * dot);        // exactly rounded RN(2*dot)
            float u = __fadd_rn(zsq, -m);
            float v = __fadd_rn(u, g_esq[c]);
            if (v < bv) { bv = v; bi = c; }      // ascending c -> lowest index on ties
        }
        sv[t] = bv; si[t] = bi;
        __syncthreads();
        for (int s = 128; s > 0; s >>= 1) {
            if (t < s) {
                float v = sv[t + s]; int id = si[t + s];
                if (v < sv[t] || (v == sv[t] && id < si[t])) { sv[t] = v; si[t] = id; }
            }
            __syncthreads();
        }
        if (t == 0) {
            codes_i[row] = si[0];
            codes_f[row] = (float)si[0];
        }
        __syncthreads();
    }
}

// ---------------------------------------------------------------------------
// Kernel 2: gather z_q, commit-loss partials, scatter embed_sum / counts
// ---------------------------------------------------------------------------
__global__ __launch_bounds__(DDIM) void k2_gather_scatter(const float* __restrict__ z,
                                                          const float* __restrict__ emb,
                                                          const int* __restrict__ codes,
                                                          float* __restrict__ zq_out) {
    __shared__ float red[DDIM];
    const int t = threadIdx.x;
    const int row0 = blockIdx.x * 8;
    float lsum = 0.0f;
#pragma unroll
    for (int r = 0; r < 8; r++) {
        int row = row0 + r;
        int c = codes[row];
        float zv = z[(size_t)row * DDIM + t];
        float ev = emb[(size_t)c * DDIM + t];
        zq_out[(size_t)row * DDIM + t] = ev;    // straight-through fwd == z_q
        float d = zv - ev;
        lsum += d * d;
        atomicAdd(&g_embed_sum[(size_t)c * DDIM + t], zv);
        if (t == 0) atomicAdd(&g_cs_batch[c], 1.0f);
    }
    red[t] = lsum;
    __syncthreads();
    for (int s = DDIM / 2; s > 0; s >>= 1) {
        if (t < s) red[t] += red[t + s];
        __syncthreads();
    }
    if (t == 0) atomicAdd(&g_loss, (double)red[0]);
}

// ---------------------------------------------------------------------------
// Kernel 3: new_cluster_size + n-sum + vq_loss (single block)
// ---------------------------------------------------------------------------
__global__ __launch_bounds__(KCODES) void k3_cluster(const float* __restrict__ cs_in,
                                                     float* __restrict__ cs_out,
                                                     float* __restrict__ loss_out,
                                                     float inv_nd) {
    __shared__ float red[KCODES];
    int t = threadIdx.x;
    float ncs = cs_in[t] * DECAYF + g_cs_batch[t] * ONE_MINUS_DECAY;
    cs_out[t] = ncs;
    red[t] = ncs;
    __syncthreads();
    for (int s = KCODES / 2; s > 0; s >>= 1) {
        if (t < s) red[t] += red[t + s];
        __syncthreads();
    }
    if (t == 0) {
        g_nsum = red[0];
        loss_out[0] = BETAF * (float)(g_loss * (double)inv_nd);
    }
}

// ---------------------------------------------------------------------------
// Kernel 4: new_embed_avg + smoothed normalize -> new_embedding
// ---------------------------------------------------------------------------
__global__ __launch_bounds__(DDIM) void k4_embed(const float* __restrict__ avg_in,
                                                 const float* __restrict__ cs_out,
                                                 float* __restrict__ avg_out,
                                                 float* __restrict__ emb_out) {
    int k = blockIdx.x;
    int t = threadIdx.x;
    size_t idx = (size_t)k * DDIM + t;
    float na = avg_in[idx] * DECAYF + g_embed_sum[idx] * ONE_MINUS_DECAY;
    avg_out[idx] = na;
    float n = g_nsum;
    float css = (cs_out[k] + EPSF) / (n + (float)KCODES * EPSF) * n;
    emb_out[idx] = na / css;
}

// ---------------------------------------------------------------------------
extern "C" void kernel_launch(void* const* d_in, const int* in_sizes, int n_in,
                              void* d_out, int out_size) {
    const float* z_e  = (const float*)d_in[0];  // [N, D]
    const float* emb  = (const float*)d_in[1];  // [K, D]
    const float* cs   = (const float*)d_in[2];  // [K]
    const float* eavg = (const float*)d_in[3];  // [K, D]

    const int n_ze = in_sizes[0];               // N*D
    const int KD   = in_sizes[1];               // K*D
    const int Kk   = in_sizes[2];               // K
    const int D    = KD / Kk;
    const int N    = n_ze / D;

    float* out = (float*)d_out;
    // Tuple order: z_q_st, vq_loss, codes, new_embedding, new_cluster_size, new_embed_avg
    float* o_zq    = out;
    float* o_loss  = out + (size_t)n_ze;
    float* o_codes = o_loss + 1;
    float* o_emb   = o_codes + N;
    float* o_cs    = o_emb + KD;
    float* o_avg   = o_cs + Kk;

    int* codes_dev;
    cudaGetSymbolAddress((void**)&codes_dev, g_codes);
    __nv_bfloat16 *zh_dev, *zl_dev, *eh_dev, *el_dev;
    cudaGetSymbolAddress((void**)&zh_dev, g_zh);
    cudaGetSymbolAddress((void**)&zl_dev, g_zl);
    cudaGetSymbolAddress((void**)&eh_dev, g_eh);
    cudaGetSymbolAddress((void**)&el_dev, g_el);

    k_split<<<n_ze / 1024, 256>>>(z_e, zh_dev, zl_dev);
    k_split<<<KD / 1024, 256>>>(emb, eh_dev, el_dev);
    k0_esq<<<Kk, D>>>(emb);
    k0_zsq<<<N / 8, 256>>>(z_e);
    k1_mma<<<N / 128, 256>>>(codes_dev, o_codes);
    k1_flag<<<N / 256, 256>>>();
    k1_refine<<<128, 256>>>(z_e, emb, codes_dev, o_codes);
    k2_gather_scatter<<<N / 8, D>>>(z_e, emb, codes_dev, o_zq);
    k3_cluster<<<1, Kk>>>(cs, o_cs, o_loss, 1.0f / (float)n_ze);
    k4_embed<<<Kk, D>>>(eavg, o_cs, o_avg, o_emb);
}

// round 6
// speedup vs baseline: 1.6384x; 1.0571x over previous
#include <cuda_runtime.h>
#include <cuda_bf16.h>
#include <stdint.h>

// Problem constants
#define KCODES 1024
#define DDIM   256
#define NROWS  65536
#define DECAYF 0.99f
#define ONE_MINUS_DECAY 0.01f
#define BETAF  0.25f
#define EPSF   1e-5f
#define GAPF   2e-3f      // flag threshold: covers max bf16-split dot error w/ margin

// Scratch (__device__ globals; no allocations allowed)
__device__ __align__(16) __nv_bfloat16 g_zh[NROWS * DDIM];
__device__ __align__(16) __nv_bfloat16 g_zl[NROWS * DDIM];
__device__ __align__(16) __nv_bfloat16 g_eh[KCODES * DDIM];
__device__ __align__(16) __nv_bfloat16 g_el[KCODES * DDIM];
__device__ float  g_esq[KCODES];
__device__ float  g_zsq[NROWS];
__device__ int    g_codes[NROWS];
__device__ int    g_flag_list[NROWS];
__device__ int    g_flag_cnt;
__device__ float  g_cs_batch[KCODES];
__device__ float  g_embed_sum[KCODES * DDIM];
__device__ double g_loss;
__device__ float  g_nsum;

// ---------------------------------------------------------------------------
// k_init: zero scatter buffers + counters. 256 blocks x 256 thr.
// ---------------------------------------------------------------------------
__global__ __launch_bounds__(256) void k_init() {
    int tid = threadIdx.x;
    int idx = blockIdx.x * 256 + tid;          // float4 index into embed_sum
    ((float4*)g_embed_sum)[idx] = make_float4(0.f, 0.f, 0.f, 0.f);
    if (blockIdx.x == 0) {
        ((float4*)g_cs_batch)[tid] = make_float4(0.f, 0.f, 0.f, 0.f);
        if (tid == 0) { g_loss = 0.0; g_nsum = 0.0f; g_flag_cnt = 0; }
    }
}

// ---------------------------------------------------------------------------
// k_split_sq: fp32 -> bf16 hi + bf16 lo (residual), fused fp64 row sum-of-sq.
// Block 256 thr = 4 rows (64 float4 per row).
// ---------------------------------------------------------------------------
__global__ __launch_bounds__(256) void k_split_sq(const float* __restrict__ src,
                                                  __nv_bfloat16* __restrict__ h,
                                                  __nv_bfloat16* __restrict__ l,
                                                  float* __restrict__ sq) {
    __shared__ double red[256];
    int tid = threadIdx.x;
    int idx = blockIdx.x * 256 + tid;          // float4 index
    float4 v = ((const float4*)src)[idx];
    __nv_bfloat16 h0 = __float2bfloat16_rn(v.x);
    __nv_bfloat16 h1 = __float2bfloat16_rn(v.y);
    __nv_bfloat16 h2 = __float2bfloat16_rn(v.z);
    __nv_bfloat16 h3 = __float2bfloat16_rn(v.w);
    __nv_bfloat16 l0 = __float2bfloat16_rn(v.x - __bfloat162float(h0));
    __nv_bfloat16 l1 = __float2bfloat16_rn(v.y - __bfloat162float(h1));
    __nv_bfloat16 l2 = __float2bfloat16_rn(v.z - __bfloat162float(h2));
    __nv_bfloat16 l3 = __float2bfloat16_rn(v.w - __bfloat162float(h3));
    __nv_bfloat162* hp = reinterpret_cast<__nv_bfloat162*>(h) + idx * 2;
    __nv_bfloat162* lp = reinterpret_cast<__nv_bfloat162*>(l) + idx * 2;
    __nv_bfloat162 a; a.x = h0; a.y = h1; hp[0] = a;
    __nv_bfloat162 b; b.x = h2; b.y = h3; hp[1] = b;
    __nv_bfloat162 c; c.x = l0; c.y = l1; lp[0] = c;
    __nv_bfloat162 d; d.x = l2; d.y = l3; lp[1] = d;

    red[tid] = (double)v.x * v.x + (double)v.y * v.y
             + (double)v.z * v.z + (double)v.w * v.w;
    __syncthreads();
#pragma unroll
    for (int s = 32; s > 0; s >>= 1) {
        if ((tid & 63) < s) red[tid] += red[tid + s];
        __syncthreads();
    }
    if ((tid & 63) == 0) sq[idx >> 6] = (float)red[tid];
}

// ---------------------------------------------------------------------------
// async-copy / mma helpers
// ---------------------------------------------------------------------------
__device__ __forceinline__ void cp_async16(uint32_t dst, const void* src) {
    asm volatile("cp.async.cg.shared.global [%0], [%1], 16;" :: "r"(dst), "l"(src));
}
__device__ __forceinline__ void cp_commit() {
    asm volatile("cp.async.commit_group;");
}
template <int N> __device__ __forceinline__ void cp_wait() {
    asm volatile("cp.async.wait_group %0;" :: "n"(N));
}
__device__ __forceinline__ void ldsm_x4(uint32_t& r0, uint32_t& r1, uint32_t& r2, uint32_t& r3,
                                        uint32_t addr) {
    asm volatile("ldmatrix.sync.aligned.m8n8.x4.shared.b16 {%0,%1,%2,%3}, [%4];"
                 : "=r"(r0), "=r"(r1), "=r"(r2), "=r"(r3) : "r"(addr));
}
__device__ __forceinline__ void ldsm_x2(uint32_t& r0, uint32_t& r1, uint32_t addr) {
    asm volatile("ldmatrix.sync.aligned.m8n8.x2.shared.b16 {%0,%1}, [%2];"
                 : "=r"(r0), "=r"(r1) : "r"(addr));
}
__device__ __forceinline__ void mma_bf16(float* cfr, uint32_t a0, uint32_t a1, uint32_t a2,
                                         uint32_t a3, uint32_t b0, uint32_t b1) {
    asm volatile("mma.sync.aligned.m16n8k16.row.col.f32.bf16.bf16.f32 "
                 "{%0,%1,%2,%3}, {%4,%5,%6,%7}, {%8,%9}, {%0,%1,%2,%3};"
                 : "+f"(cfr[0]), "+f"(cfr[1]), "+f"(cfr[2]), "+f"(cfr[3])
                 : "r"(a0), "r"(a1), "r"(a2), "r"(a3), "r"(b0), "r"(b1));
}
__device__ __forceinline__ void upd(float& b, float& s, int& i, float v, int col) {
    if (v < b) { s = b; b = v; i = col; }
    else if (v < s) { s = v; }
}
__device__ __forceinline__ void merge2(float& b, float& s, int& i,
                                       float ob, float os, int oi) {
    float ns = fminf(s, os);
    if (ob < b || (ob == b && oi < i)) { ns = fminf(ns, b); b = ob; i = oi; }
    else { ns = fminf(ns, ob); }
    s = ns;
}

// ---------------------------------------------------------------------------
// Kernel 1: 3-term bf16-split GEMM (zh*eh + zl*eh + zh*el) via mma.sync,
// cp.async double-buffered k-chunks, fused quantized-distance argmin epilogue,
// fused near-tie flag compaction.
// Block: 128 rows. 8 passes of 128 codes, k-chunk 32. 256 thr = 8 warps (4m x 2n).
// ---------------------------------------------------------------------------
#define PITCH_B   80                 // bytes per smem row (64 data + 16 pad)
#define TILE_ST   (128 * PITCH_B)    // 10240 B per tile
#define STAGE_ST  (4 * TILE_ST)      // 40960 B per stage (Ah, Al, Bh, Bl)
#define SMEM_TILES (2 * STAGE_ST)    // 81920 B
#define SMEM_K1   (SMEM_TILES + 512 + 3 * 1024)   // + sEsq + sFb/sFs/sFi

__global__ __launch_bounds__(256) void k1_mma(int* __restrict__ codes_i,
                                              float* __restrict__ codes_f) {
    extern __shared__ char smem[];
    float* sEsq = (float*)(smem + SMEM_TILES);
    float* sFb  = (float*)(smem + SMEM_TILES + 512);
    float* sFs  = (float*)(smem + SMEM_TILES + 512 + 1024);
    int*   sFi  = (int*)  (smem + SMEM_TILES + 512 + 2048);

    const int tid  = threadIdx.x;
    const int lane = tid & 31;
    const int warp = tid >> 5;
    const int wm   = warp & 3;
    const int wn   = warp >> 2;
    const int row0 = blockIdx.x * 128;
    const uint32_t sbase = (uint32_t)__cvta_generic_to_shared(smem);

    const int rbase = wm * 32 + (lane >> 2);
    float zs[4];
#pragma unroll
    for (int r = 0; r < 4; r++) zs[r] = g_zsq[row0 + rbase + r * 8];

    float best[4], secv[4];
    int   bidx[4];
#pragma unroll
    for (int r = 0; r < 4; r++) { best[r] = 3.0e38f; secv[r] = 3.0e38f; bidx[r] = 0x7fffffff; }

    // cp.async issue for one k-chunk into stage st
    auto issue = [&](int kc, int st, int n0) {
        const int k0 = kc * 32;
#pragma unroll
        for (int it = 0; it < 8; it++) {
            int tile = it >> 1;                         // 0..3 (tid < 256)
            int rr   = ((tid >> 2) + it * 64) & 127;
            int sub  = tid & 3;
            const __nv_bfloat16* gp;
            if      (tile == 0) gp = g_zh + (size_t)(row0 + rr) * DDIM;
            else if (tile == 1) gp = g_zl + (size_t)(row0 + rr) * DDIM;
            else if (tile == 2) gp = g_eh + (size_t)(/*n0*/ n0 + rr) * DDIM;
            else                gp = g_el + (size_t)(n0 + rr) * DDIM;
            uint32_t dst = sbase + st * STAGE_ST + tile * TILE_ST + rr * PITCH_B + sub * 16;
            cp_async16(dst, gp + k0 + sub * 8);
        }
        cp_commit();
    };

    for (int n0 = 0; n0 < KCODES; n0 += 128) {
        __syncthreads();                      // prev-pass epilogue readers done
        if (tid < 128) sEsq[tid] = g_esq[n0 + tid];

        float acc[2][8][4];
#pragma unroll
        for (int mt = 0; mt < 2; mt++)
#pragma unroll
            for (int nt = 0; nt < 8; nt++)
#pragma unroll
                for (int q = 0; q < 4; q++) acc[mt][nt][q] = 0.0f;

        issue(0, 0, n0);

        for (int kc = 0; kc < 8; kc++) {
            if (kc < 7) issue(kc + 1, (kc + 1) & 1, n0);
            if (kc < 7) cp_wait<1>(); else cp_wait<0>();
            __syncthreads();

            const int st = kc & 1;
            const uint32_t bAh = sbase + st * STAGE_ST;
            const uint32_t bAl = bAh + TILE_ST;
            const uint32_t bBh = bAh + 2 * TILE_ST;
            const uint32_t bBl = bAh + 3 * TILE_ST;

#pragma unroll
            for (int ks = 0; ks < 2; ks++) {
                const uint32_t koff = ks * 32;
                uint32_t Ah[2][4], Al[2][4];
#pragma unroll
                for (int mt = 0; mt < 2; mt++) {
                    uint32_t off = (uint32_t)(wm * 32 + mt * 16 + (lane & 15)) * PITCH_B
                                 + koff + ((lane >> 4) & 1) * 16;
                    ldsm_x4(Ah[mt][0], Ah[mt][1], Ah[mt][2], Ah[mt][3], bAh + off);
                    ldsm_x4(Al[mt][0], Al[mt][1], Al[mt][2], Al[mt][3], bAl + off);
                }
                uint32_t Bh[8][2], Bl[8][2];
#pragma unroll
                for (int nt = 0; nt < 8; nt++) {
                    uint32_t off = (uint32_t)(wn * 64 + nt * 8 + (lane & 7)) * PITCH_B
                                 + koff + ((lane >> 3) & 1) * 16;
                    ldsm_x2(Bh[nt][0], Bh[nt][1], bBh + off);
                    ldsm_x2(Bl[nt][0], Bl[nt][1], bBl + off);
                }
#pragma unroll
                for (int mt = 0; mt < 2; mt++)
#pragma unroll
                    for (int nt = 0; nt < 8; nt++) {
                        mma_bf16(acc[mt][nt], Ah[mt][0], Ah[mt][1], Ah[mt][2], Ah[mt][3],
                                 Bh[nt][0], Bh[nt][1]);
                        mma_bf16(acc[mt][nt], Al[mt][0], Al[mt][1], Al[mt][2], Al[mt][3],
                                 Bh[nt][0], Bh[nt][1]);
                        mma_bf16(acc[mt][nt], Ah[mt][0], Ah[mt][1], Ah[mt][2], Ah[mt][3],
                                 Bl[nt][0], Bl[nt][1]);
                    }
            }
            __syncthreads();                  // all readers done before stage reuse
        }

        // Epilogue: quantized distance + top-2 fold (cols ascending per thread)
        const int qc = lane & 3;
#pragma unroll
        for (int nt = 0; nt < 8; nt++) {
#pragma unroll
            for (int cp = 0; cp < 2; cp++) {
                int cl  = wn * 64 + nt * 8 + qc * 2 + cp;
                float esq = sEsq[cl];
                int col = n0 + cl;
                float v;
                v = __fadd_rn(__fadd_rn(zs[0], -2.0f * acc[0][nt][cp]),     esq);
                upd(best[0], secv[0], bidx[0], v, col);
                v = __fadd_rn(__fadd_rn(zs[1], -2.0f * acc[0][nt][2 + cp]), esq);
                upd(best[1], secv[1], bidx[1], v, col);
                v = __fadd_rn(__fadd_rn(zs[2], -2.0f * acc[1][nt][cp]),     esq);
                upd(best[2], secv[2], bidx[2], v, col);
                v = __fadd_rn(__fadd_rn(zs[3], -2.0f * acc[1][nt][2 + cp]), esq);
                upd(best[3], secv[3], bidx[3], v, col);
            }
        }
    }

    // Quad reduction (lanes within group-of-4 share rows, hold different cols)
#pragma unroll
    for (int off = 1; off <= 2; off <<= 1) {
#pragma unroll
        for (int r = 0; r < 4; r++) {
            float ob = __shfl_xor_sync(0xffffffffu, best[r], off);
            float os = __shfl_xor_sync(0xffffffffu, secv[r], off);
            int   oi = __shfl_xor_sync(0xffffffffu, bidx[r], off);
            merge2(best[r], secv[r], bidx[r], ob, os, oi);
        }
    }
    if ((lane & 3) == 0) {
#pragma unroll
        for (int r = 0; r < 4; r++) {
            int rl = wm * 32 + (lane >> 2) + r * 8;
            sFb[rl * 2 + wn] = best[r];
            sFs[rl * 2 + wn] = secv[r];
            sFi[rl * 2 + wn] = bidx[r];
        }
    }
    __syncthreads();
    if (tid < 128) {
        float b = sFb[tid * 2], s = sFs[tid * 2];
        int   i = sFi[tid * 2];
        merge2(b, s, i, sFb[tid * 2 + 1], sFs[tid * 2 + 1], sFi[tid * 2 + 1]);
        int row = row0 + tid;
        codes_i[row] = i;
        codes_f[row] = (float)i;
        if (s - b <= GAPF) {                  // fused near-tie flag compaction
            int p = atomicAdd(&g_flag_cnt, 1);
            g_flag_list[p] = row;
        }
    }
}

// ---------------------------------------------------------------------------
// k1_refine: exact fp64-dot recompute for flagged rows (fixed small grid).
// ---------------------------------------------------------------------------
__global__ __launch_bounds__(256) void k1_refine(const float* __restrict__ z,
                                                 const float* __restrict__ emb,
                                                 int* __restrict__ codes_i,
                                                 float* __restrict__ codes_f) {
    __shared__ float zrow[DDIM];
    __shared__ float sv[256];
    __shared__ int   si[256];
    int t = threadIdx.x;
    int cnt = g_flag_cnt;
    for (int fi = blockIdx.x; fi < cnt; fi += gridDim.x) {
        int row = g_flag_list[fi];
        zrow[t] = z[(size_t)row * DDIM + t];
        __syncthreads();

        float zsq = g_zsq[row];
        float bv = 3.0e38f;
        int   bi = 0x7fffffff;
        for (int c = t; c < KCODES; c += 256) {
            const float4* e4 = (const float4*)(emb + (size_t)c * DDIM);
            const float4* z4 = (const float4*)zrow;
            double dot = 0.0;
#pragma unroll 8
            for (int q = 0; q < DDIM / 4; q++) {
                float4 ev = e4[q];
                float4 zv = z4[q];
                dot += (double)zv.x * ev.x + (double)zv.y * ev.y
                     + (double)zv.z * ev.z + (double)zv.w * ev.w;
            }
            float m = (float)(2.0 * dot);        // exactly rounded RN(2*dot)
            float u = __fadd_rn(zsq, -m);
            float v = __fadd_rn(u, g_esq[c]);
            if (v < bv) { bv = v; bi = c; }      // ascending c -> lowest index on ties
        }
        sv[t] = bv; si[t] = bi;
        __syncthreads();
        for (int s = 128; s > 0; s >>= 1) {
            if (t < s) {
                float v = sv[t + s]; int id = si[t + s];
                if (v < sv[t] || (v == sv[t] && id < si[t])) { sv[t] = v; si[t] = id; }
            }
            __syncthreads();
        }
        if (t == 0) {
            codes_i[row] = si[0];
            codes_f[row] = (float)si[0];
        }
        __syncthreads();
    }
}

// ---------------------------------------------------------------------------
// Kernel 2: gather z_q, commit-loss partials, scatter embed_sum / counts
// ---------------------------------------------------------------------------
__global__ __launch_bounds__(DDIM) void k2_gather_scatter(const float* __restrict__ z,
                                                          const float* __restrict__ emb,
                                                          const int* __restrict__ codes,
                                                          float* __restrict__ zq_out) {
    __shared__ float red[DDIM];
    const int t = threadIdx.x;
    const int row0 = blockIdx.x * 8;
    float lsum = 0.0f;
#pragma unroll
    for (int r = 0; r < 8; r++) {
        int row = row0 + r;
        int c = codes[row];
        float zv = z[(size_t)row * DDIM + t];
        float ev = emb[(size_t)c * DDIM + t];
        zq_out[(size_t)row * DDIM + t] = ev;    // straight-through fwd == z_q
        float d = zv - ev;
        lsum += d * d;
        atomicAdd(&g_embed_sum[(size_t)c * DDIM + t], zv);
        if (t == 0) atomicAdd(&g_cs_batch[c], 1.0f);
    }
    red[t] = lsum;
    __syncthreads();
    for (int s = DDIM / 2; s > 0; s >>= 1) {
        if (t < s) red[t] += red[t + s];
        __syncthreads();
    }
    if (t == 0) atomicAdd(&g_loss, (double)red[0]);
}

// ---------------------------------------------------------------------------
// Kernel 3: new_cluster_size + n-sum + vq_loss (single block)
// ---------------------------------------------------------------------------
__global__ __launch_bounds__(KCODES) void k3_cluster(const float* __restrict__ cs_in,
                                                     float* __restrict__ cs_out,
                                                     float* __restrict__ loss_out,
                                                     float inv_nd) {
    __shared__ float red[KCODES];
    int t = threadIdx.x;
    float ncs = cs_in[t] * DECAYF + g_cs_batch[t] * ONE_MINUS_DECAY;
    cs_out[t] = ncs;
    red[t] = ncs;
    __syncthreads();
    for (int s = KCODES / 2; s > 0; s >>= 1) {
        if (t < s) red[t] += red[t + s];
        __syncthreads();
    }
    if (t == 0) {
        g_nsum = red[0];
        loss_out[0] = BETAF * (float)(g_loss * (double)inv_nd);
    }
}

// ---------------------------------------------------------------------------
// Kernel 4: new_embed_avg + smoothed normalize -> new_embedding
// ---------------------------------------------------------------------------
__global__ __launch_bounds__(DDIM) void k4_embed(const float* __restrict__ avg_in,
                                                 const float* __restrict__ cs_out,
                                                 float* __restrict__ avg_out,
                                                 float* __restrict__ emb_out) {
    int k = blockIdx.x;
    int t = threadIdx.x;
    size_t idx = (size_t)k * DDIM + t;
    float na = avg_in[idx] * DECAYF + g_embed_sum[idx] * ONE_MINUS_DECAY;
    avg_out[idx] = na;
    float n = g_nsum;
    float css = (cs_out[k] + EPSF) / (n + (float)KCODES * EPSF) * n;
    emb_out[idx] = na / css;
}

// ---------------------------------------------------------------------------
extern "C" void kernel_launch(void* const* d_in, const int* in_sizes, int n_in,
                              void* d_out, int out_size) {
    const float* z_e  = (const float*)d_in[0];  // [N, D]
    const float* emb  = (const float*)d_in[1];  // [K, D]
    const float* cs   = (const float*)d_in[2];  // [K]
    const float* eavg = (const float*)d_in[3];  // [K, D]

    const int n_ze = in_sizes[0];               // N*D
    const int KD   = in_sizes[1];               // K*D
    const int Kk   = in_sizes[2];               // K
    const int D    = KD / Kk;
    const int N    = n_ze / D;

    float* out = (float*)d_out;
    // Tuple order: z_q_st, vq_loss, codes, new_embedding, new_cluster_size, new_embed_avg
    float* o_zq    = out;
    float* o_loss  = out + (size_t)n_ze;
    float* o_codes = o_loss + 1;
    float* o_emb   = o_codes + N;
    float* o_cs    = o_emb + KD;
    float* o_avg   = o_cs + Kk;

    int* codes_dev;
    cudaGetSymbolAddress((void**)&codes_dev, g_codes);
    __nv_bfloat16 *zh_dev, *zl_dev, *eh_dev, *el_dev;
    cudaGetSymbolAddress((void**)&zh_dev, g_zh);
    cudaGetSymbolAddress((void**)&zl_dev, g_zl);
    cudaGetSymbolAddress((void**)&eh_dev, g_eh);
    cudaGetSymbolAddress((void**)&el_dev, g_el);
    float *zsq_dev, *esq_dev;
    cudaGetSymbolAddress((void**)&zsq_dev, g_zsq);
    cudaGetSymbolAddress((void**)&esq_dev, g_esq);

    static bool attr_set = false;
    if (!attr_set) {
        cudaFuncSetAttribute(k1_mma, cudaFuncAttributeMaxDynamicSharedMemorySize, SMEM_K1);
        attr_set = true;
    }

    k_init<<<KD / 1024, 256>>>();
    k_split_sq<<<n_ze / 1024, 256>>>(z_e, zh_dev, zl_dev, zsq_dev);
    k_split_sq<<<KD / 1024, 256>>>(emb, eh_dev, el_dev, esq_dev);
    k1_mma<<<N / 128, 256, SMEM_K1>>>(codes_dev, o_codes);
    k1_refine<<<128, 256>>>(z_e, emb, codes_dev, o_codes);
    k2_gather_scatter<<<N / 8, D>>>(z_e, emb, codes_dev, o_zq);
    k3_cluster<<<1, Kk>>>(cs, o_cs, o_loss, 1.0f / (float)n_ze);
    k4_embed<<<Kk, D>>>(eavg, o_cs, o_avg, o_emb);
}

// round 10
// speedup vs baseline: 1.7777x; 1.0850x over previous
#include <cuda_runtime.h>
#include <cuda_bf16.h>
#include <stdint.h>

// Problem constants
#define KCODES 1024
#define DDIM   256
#define NROWS  65536
#define DECAYF 0.99f
#define ONE_MINUS_DECAY 0.01f
#define BETAF  0.25f
#define EPSF   1e-5f
#define GAPF   2e-3f      // flag threshold: covers max bf16-split dot error w/ margin

// Scratch (__device__ globals; no allocations allowed)
__device__ __align__(16) __nv_bfloat16 g_zh[NROWS * DDIM];
__device__ __align__(16) __nv_bfloat16 g_zl[NROWS * DDIM];
__device__ __align__(16) __nv_bfloat16 g_eh[KCODES * DDIM];
__device__ __align__(16) __nv_bfloat16 g_el[KCODES * DDIM];
__device__ float  g_esq[KCODES];
__device__ float  g_zsq[NROWS];
__device__ int    g_codes[NROWS];
__device__ int    g_flag_list[NROWS];
__device__ int    g_flag_cnt;
__device__ float  g_cs_batch[KCODES];
__device__ float  g_embed_sum[KCODES * DDIM];
__device__ double g_loss;
__device__ float  g_nsum;

// ---------------------------------------------------------------------------
// k_init: zero scatter buffers + counters. 256 blocks x 256 thr.
// ---------------------------------------------------------------------------
__global__ __launch_bounds__(256) void k_init() {
    int tid = threadIdx.x;
    int idx = blockIdx.x * 256 + tid;          // float4 index into embed_sum
    ((float4*)g_embed_sum)[idx] = make_float4(0.f, 0.f, 0.f, 0.f);
    if (blockIdx.x == 0) {
        ((float4*)g_cs_batch)[tid] = make_float4(0.f, 0.f, 0.f, 0.f);
        if (tid == 0) { g_loss = 0.0; g_nsum = 0.0f; g_flag_cnt = 0; }
    }
}

// ---------------------------------------------------------------------------
// k_split_sq: fp32 -> bf16 hi + bf16 lo (residual), fused fp64 row sum-of-sq.
// Block 256 thr = 4 rows (64 float4 per row = 2 warps per row).
// ---------------------------------------------------------------------------
__global__ __launch_bounds__(256) void k_split_sq(const float* __restrict__ src,
                                                  __nv_bfloat16* __restrict__ h,
                                                  __nv_bfloat16* __restrict__ l,
                                                  float* __restrict__ sq) {
    __shared__ double part[8];
    int tid = threadIdx.x;
    int idx = blockIdx.x * 256 + tid;          // float4 index
    float4 v = ((const float4*)src)[idx];
    __nv_bfloat16 h0 = __float2bfloat16_rn(v.x);
    __nv_bfloat16 h1 = __float2bfloat16_rn(v.y);
    __nv_bfloat16 h2 = __float2bfloat16_rn(v.z);
    __nv_bfloat16 h3 = __float2bfloat16_rn(v.w);
    __nv_bfloat16 l0 = __float2bfloat16_rn(v.x - __bfloat162float(h0));
    __nv_bfloat16 l1 = __float2bfloat16_rn(v.y - __bfloat162float(h1));
    __nv_bfloat16 l2 = __float2bfloat16_rn(v.z - __bfloat162float(h2));
    __nv_bfloat16 l3 = __float2bfloat16_rn(v.w - __bfloat162float(h3));
    __nv_bfloat162* hp = reinterpret_cast<__nv_bfloat162*>(h) + idx * 2;
    __nv_bfloat162* lp = reinterpret_cast<__nv_bfloat162*>(l) + idx * 2;
    __nv_bfloat162 a; a.x = h0; a.y = h1; hp[0] = a;
    __nv_bfloat162 b; b.x = h2; b.y = h3; hp[1] = b;
    __nv_bfloat162 c; c.x = l0; c.y = l1; lp[0] = c;
    __nv_bfloat162 d; d.x = l2; d.y = l3; lp[1] = d;

    double s = (double)v.x * v.x + (double)v.y * v.y
             + (double)v.z * v.z + (double)v.w * v.w;
#pragma unroll
    for (int off = 16; off > 0; off >>= 1)
        s += __shfl_down_sync(0xffffffffu, s, off);
    int warp = tid >> 5;
    if ((tid & 31) == 0) part[warp] = s;
    __syncthreads();
    if (tid < 4) sq[blockIdx.x * 4 + tid] = (float)(part[tid * 2] + part[tid * 2 + 1]);
}

// ---------------------------------------------------------------------------
// async-copy / mma helpers
// ---------------------------------------------------------------------------
__device__ __forceinline__ void cp_async16(uint32_t dst, const void* src) {
    asm volatile("cp.async.cg.shared.global [%0], [%1], 16;" :: "r"(dst), "l"(src));
}
__device__ __forceinline__ void cp_commit() {
    asm volatile("cp.async.commit_group;");
}
template <int N> __device__ __forceinline__ void cp_wait() {
    asm volatile("cp.async.wait_group %0;" :: "n"(N));
}
__device__ __forceinline__ void ldsm_x4(uint32_t& r0, uint32_t& r1, uint32_t& r2, uint32_t& r3,
                                        uint32_t addr) {
    asm volatile("ldmatrix.sync.aligned.m8n8.x4.shared.b16 {%0,%1,%2,%3}, [%4];"
                 : "=r"(r0), "=r"(r1), "=r"(r2), "=r"(r3) : "r"(addr));
}
__device__ __forceinline__ void mma_bf16(float* cfr, uint32_t a0, uint32_t a1, uint32_t a2,
                                         uint32_t a3, uint32_t b0, uint32_t b1) {
    asm volatile("mma.sync.aligned.m16n8k16.row.col.f32.bf16.bf16.f32 "
                 "{%0,%1,%2,%3}, {%4,%5,%6,%7}, {%8,%9}, {%0,%1,%2,%3};"
                 : "+f"(cfr[0]), "+f"(cfr[1]), "+f"(cfr[2]), "+f"(cfr[3])
                 : "r"(a0), "r"(a1), "r"(a2), "r"(a3), "r"(b0), "r"(b1));
}
__device__ __forceinline__ void upd(float& b, float& s, int& i, float v, int col) {
    if (v < b) { s = b; b = v; i = col; }
    else if (v < s) { s = v; }
}
__device__ __forceinline__ void merge2(float& b, float& s, int& i,
                                       float ob, float os, int oi) {
    float ns = fminf(s, os);
    if (ob < b || (ob == b && oi < i)) { ns = fminf(ns, b); b = ob; i = oi; }
    else { ns = fminf(ns, ob); }
    s = ns;
}

// ---------------------------------------------------------------------------
// Kernel 1: 3-term bf16-split GEMM via mma.sync, cp.async double-buffered,
// fused quantized-distance argmin, fused flag compaction, fused loss sum.
// Block: 128 rows x passes of 128 codes; 256 thr = 8 warps (4m x 2n); 2 CTA/SM.
// ---------------------------------------------------------------------------
#define PITCH_B   80                 // bytes per smem row (64 data + 16 pad)
#define TILE_ST   (128 * PITCH_B)    // 10240 B per tile
#define STAGE_ST  (4 * TILE_ST)      // 40960 B per stage (Ah, Al, Bh, Bl)
#define SMEM_TILES (2 * STAGE_ST)    // 81920 B
#define SMEM_K1   (SMEM_TILES + 512 + 3 * 1024)

__global__ __launch_bounds__(256, 2) void k1_mma(int* __restrict__ codes_i,
                                                 float* __restrict__ codes_f) {
    extern __shared__ char smem[];
    float* sEsq = (float*)(smem + SMEM_TILES);
    float* sFb  = (float*)(smem + SMEM_TILES + 512);
    float* sFs  = (float*)(smem + SMEM_TILES + 512 + 1024);
    int*   sFi  = (int*)  (smem + SMEM_TILES + 512 + 2048);

    const int tid  = threadIdx.x;
    const int lane = tid & 31;
    const int warp = tid >> 5;
    const int wm   = warp & 3;
    const int wn   = warp >> 2;
    const int row0 = blockIdx.x * 128;
    const uint32_t sbase = (uint32_t)__cvta_generic_to_shared(smem);

    const int rbase = wm * 32 + (lane >> 2);
    float zs[4];
#pragma unroll
    for (int r = 0; r < 4; r++) zs[r] = g_zsq[row0 + rbase + r * 8];

    float best[4], secv[4];
    int   bidx[4];
#pragma unroll
    for (int r = 0; r < 4; r++) { best[r] = 3.0e38f; secv[r] = 3.0e38f; bidx[r] = 0x7fffffff; }

    auto issue = [&](int kc, int st, int n0) {
        const int k0 = kc * 32;
#pragma unroll
        for (int it = 0; it < 8; it++) {
            int tile = it >> 1;
            int rr   = ((tid >> 2) + it * 64) & 127;
            int sub  = tid & 3;
            const __nv_bfloat16* gp;
            if      (tile == 0) gp = g_zh + (size_t)(row0 + rr) * DDIM;
            else if (tile == 1) gp = g_zl + (size_t)(row0 + rr) * DDIM;
            else if (tile == 2) gp = g_eh + (size_t)(n0 + rr) * DDIM;
            else                gp = g_el + (size_t)(n0 + rr) * DDIM;
            uint32_t dst = sbase + st * STAGE_ST + tile * TILE_ST + rr * PITCH_B + sub * 16;
            cp_async16(dst, gp + k0 + sub * 8);
        }
        cp_commit();
    };

    for (int n0 = 0; n0 < KCODES; n0 += 128) {
        __syncthreads();
        if (tid < 128) sEsq[tid] = g_esq[n0 + tid];

        float acc[2][8][4];
#pragma unroll
        for (int mt = 0; mt < 2; mt++)
#pragma unroll
            for (int nt = 0; nt < 8; nt++)
#pragma unroll
                for (int q = 0; q < 4; q++) acc[mt][nt][q] = 0.0f;

        issue(0, 0, n0);

        for (int kc = 0; kc < 8; kc++) {
            if (kc < 7) issue(kc + 1, (kc + 1) & 1, n0);
            if (kc < 7) cp_wait<1>(); else cp_wait<0>();
            __syncthreads();

            const int st = kc & 1;
            const uint32_t bAh = sbase + st * STAGE_ST;
            const uint32_t bAl = bAh + TILE_ST;
            const uint32_t bBh = bAh + 2 * TILE_ST;
            const uint32_t bBl = bAh + 3 * TILE_ST;

#pragma unroll
            for (int ks = 0; ks < 2; ks++) {
                const uint32_t koff = ks * 32;
                uint32_t Ah[2][4], Al[2][4];
#pragma unroll
                for (int mt = 0; mt < 2; mt++) {
                    uint32_t off = (uint32_t)(wm * 32 + mt * 16 + (lane & 15)) * PITCH_B
                                 + koff + ((lane >> 4) & 1) * 16;
                    ldsm_x4(Ah[mt][0], Ah[mt][1], Ah[mt][2], Ah[mt][3], bAh + off);
                    ldsm_x4(Al[mt][0], Al[mt][1], Al[mt][2], Al[mt][3], bAl + off);
                }
                // B: x4 ldmatrix covers 2 n-tiles (lanes grouped by 8)
                const int g  = lane >> 3;
                const int rb = lane & 7;
#pragma unroll
                for (int ntp = 0; ntp < 4; ntp++) {
                    uint32_t nrow = (uint32_t)(wn * 64 + (ntp * 2 + (g >> 1)) * 8 + rb);
                    uint32_t off  = nrow * PITCH_B + koff + (g & 1) * 16;
                    uint32_t Bh0, Bh1, Bh2, Bh3, Bl0, Bl1, Bl2, Bl3;
                    ldsm_x4(Bh0, Bh1, Bh2, Bh3, bBh + off);
                    ldsm_x4(Bl0, Bl1, Bl2, Bl3, bBl + off);
                    const int nt0 = ntp * 2, nt1 = nt0 + 1;
#pragma unroll
                    for (int mt = 0; mt < 2; mt++) {
                        mma_bf16(acc[mt][nt0], Ah[mt][0], Ah[mt][1], Ah[mt][2], Ah[mt][3], Bh0, Bh1);
                        mma_bf16(acc[mt][nt0], Al[mt][0], Al[mt][1], Al[mt][2], Al[mt][3], Bh0, Bh1);
                        mma_bf16(acc[mt][nt0], Ah[mt][0], Ah[mt][1], Ah[mt][2], Ah[mt][3], Bl0, Bl1);
                        mma_bf16(acc[mt][nt1], Ah[mt][0], Ah[mt][1], Ah[mt][2], Ah[mt][3], Bh2, Bh3);
                        mma_bf16(acc[mt][nt1], Al[mt][0], Al[mt][1], Al[mt][2], Al[mt][3], Bh2, Bh3);
                        mma_bf16(acc[mt][nt1], Ah[mt][0], Ah[mt][1], Ah[mt][2], Ah[mt][3], Bl2, Bl3);
                    }
                }
            }
            __syncthreads();
        }

        // Epilogue: quantized distance + top-2 fold (cols ascending per thread)
        const int qc = lane & 3;
#pragma unroll
        for (int nt = 0; nt < 8; nt++) {
#pragma unroll
            for (int cp = 0; cp < 2; cp++) {
                int cl  = wn * 64 + nt * 8 + qc * 2 + cp;
                float esq = sEsq[cl];
                int col = n0 + cl;
                float v;
                v = __fadd_rn(__fadd_rn(zs[0], -2.0f * acc[0][nt][cp]),     esq);
                upd(best[0], secv[0], bidx[0], v, col);
                v = __fadd_rn(__fadd_rn(zs[1], -2.0f * acc[0][nt][2 + cp]), esq);
                upd(best[1], secv[1], bidx[1], v, col);
                v = __fadd_rn(__fadd_rn(zs[2], -2.0f * acc[1][nt][cp]),     esq);
                upd(best[2], secv[2], bidx[2], v, col);
                v = __fadd_rn(__fadd_rn(zs[3], -2.0f * acc[1][nt][2 + cp]), esq);
                upd(best[3], secv[3], bidx[3], v, col);
            }
        }
    }

    // Quad reduction (lanes within group-of-4 share rows, hold different cols)
#pragma unroll
    for (int off = 1; off <= 2; off <<= 1) {
#pragma unroll
        for (int r = 0; r < 4; r++) {
            float ob = __shfl_xor_sync(0xffffffffu, best[r], off);
            float os = __shfl_xor_sync(0xffffffffu, secv[r], off);
            int   oi = __shfl_xor_sync(0xffffffffu, bidx[r], off);
            merge2(best[r], secv[r], bidx[r], ob, os, oi);
        }
    }
    if ((lane & 3) == 0) {
#pragma unroll
        for (int r = 0; r < 4; r++) {
            int rl = wm * 32 + (lane >> 2) + r * 8;
            sFb[rl * 2 + wn] = best[r];
            sFs[rl * 2 + wn] = secv[r];
            sFi[rl * 2 + wn] = bidx[r];
        }
    }
    __syncthreads();
    float* sLoss = sFs;                       // reuse after final merge reads
    if (tid < 128) {
        float b = sFb[tid * 2], s = sFs[tid * 2];
        int   i = sFi[tid * 2];
        merge2(b, s, i, sFb[tid * 2 + 1], sFs[tid * 2 + 1], sFi[tid * 2 + 1]);
        int row = row0 + tid;
        codes_i[row] = i;
        codes_f[row] = (float)i;
        if (s - b <= GAPF) {                  // near-tie flag compaction
            int p = atomicAdd(&g_flag_cnt, 1);
            g_flag_list[p] = row;
        }
        sFb[tid] = b;                         // stage for loss reduction
    }
    __syncthreads();
    if (tid < 64) sLoss[tid] = sFb[tid] + sFb[tid + 64];
    __syncthreads();
    if (tid < 32) {
        float s = sLoss[tid] + sLoss[tid + 32];
#pragma unroll
        for (int off = 16; off > 0; off >>= 1)
            s += __shfl_down_sync(0xffffffffu, s, off);
        if (tid == 0) atomicAdd(&g_loss, (double)s);
    }
}

// ---------------------------------------------------------------------------
// k1_refine: exact fp64-dot recompute for flagged rows (fixed small grid).
// ---------------------------------------------------------------------------
__global__ __launch_bounds__(256) void k1_refine(const float* __restrict__ z,
                                                 const float* __restrict__ emb,
                                                 int* __restrict__ codes_i,
                                                 float* __restrict__ codes_f) {
    __shared__ float zrow[DDIM];
    __shared__ float sv[256];
    __shared__ int   si[256];
    int t = threadIdx.x;
    int cnt = g_flag_cnt;
    for (int fi = blockIdx.x; fi < cnt; fi += gridDim.x) {
        int row = g_flag_list[fi];
        zrow[t] = z[(size_t)row * DDIM + t];
        __syncthreads();

        float zsq = g_zsq[row];
        float bv = 3.0e38f;
        int   bi = 0x7fffffff;
        for (int c = t; c < KCODES; c += 256) {
            const float4* e4 = (const float4*)(emb + (size_t)c * DDIM);
            const float4* z4 = (const float4*)zrow;
            double dot = 0.0;
#pragma unroll 8
            for (int q = 0; q < DDIM / 4; q++) {
                float4 ev = e4[q];
                float4 zv = z4[q];
                dot += (double)zv.x * ev.x + (double)zv.y * ev.y
                     + (double)zv.z * ev.z + (double)zv.w * ev.w;
            }
            float m = (float)(2.0 * dot);        // exactly rounded RN(2*dot)
            float u = __fadd_rn(zsq, -m);
            float v = __fadd_rn(u, g_esq[c]);
            if (v < bv) { bv = v; bi = c; }      // ascending c -> lowest index on ties
        }
        sv[t] = bv; si[t] = bi;
        __syncthreads();
        for (int s = 128; s > 0; s >>= 1) {
            if (t < s) {
                float v = sv[t + s]; int id = si[t + s];
                if (v < sv[t] || (v == sv[t] && id < si[t])) { sv[t] = v; si[t] = id; }
            }
            __syncthreads();
        }
        if (t == 0) {
            codes_i[row] = si[0];
            codes_f[row] = (float)si[0];
        }
        __syncthreads();
    }
}

// ---------------------------------------------------------------------------
// Kernel 2: gather z_q (float4) + scatter embed_sum / counts. No reductions.
// 256 thr = 4 rows x 64 float4-lanes. grid N/4.
// ---------------------------------------------------------------------------
__global__ __launch_bounds__(256) void k2_gather_scatter(const float* __restrict__ z,
                                                         const float* __restrict__ emb,
                                                         const int* __restrict__ codes,
                                                         float* __restrict__ zq_out) {
    int tid = threadIdx.x;
    int row = blockIdx.x * 4 + (tid >> 6);
    int q   = tid & 63;
    int c   = codes[row];
    float4 zv = ((const float4*)(z   + (size_t)row * DDIM))[q];
    float4 ev = ((const float4*)(emb + (size_t)c   * DDIM))[q];
    ((float4*)(zq_out + (size_t)row * DDIM))[q] = ev;
    float* es = g_embed_sum + (size_t)c * DDIM + q * 4;
    atomicAdd(es + 0, zv.x);
    atomicAdd(es + 1, zv.y);
    atomicAdd(es + 2, zv.z);
    atomicAdd(es + 3, zv.w);
    if (q == 0) atomicAdd(&g_cs_batch[c], 1.0f);
}

// ---------------------------------------------------------------------------
// Kernel 3: new_cluster_size + n-sum + vq_loss (single block)
// ---------------------------------------------------------------------------
__global__ __launch_bounds__(KCODES) void k3_cluster(const float* __restrict__ cs_in,
                                                     float* __restrict__ cs_out,
                                                     float* __restrict__ loss_out,
                                                     float inv_nd) {
    __shared__ float red[KCODES];
    int t = threadIdx.x;
    float ncs = cs_in[t] * DECAYF + g_cs_batch[t] * ONE_MINUS_DECAY;
    cs_out[t] = ncs;
    red[t] = ncs;
    __syncthreads();
    for (int s = KCODES / 2; s > 0; s >>= 1) {
        if (t < s) red[t] += red[t + s];
        __syncthreads();
    }
    if (t == 0) {
        g_nsum = red[0];
        loss_out[0] = BETAF * (float)(g_loss * (double)inv_nd);
    }
}

// ---------------------------------------------------------------------------
// Kernel 4: new_embed_avg + smoothed normalize -> new_embedding
// ---------------------------------------------------------------------------
__global__ __launch_bounds__(DDIM) void k4_embed(const float* __restrict__ avg_in,
                                                 const float* __restrict__ cs_out,
                                                 float* __restrict__ avg_out,
                                                 float* __restrict__ emb_out) {
    int k = blockIdx.x;
    int t = threadIdx.x;
    size_t idx = (size_t)k * DDIM + t;
    float na = avg_in[idx] * DECAYF + g_embed_sum[idx] * ONE_MINUS_DECAY;
    avg_out[idx] = na;
    float n = g_nsum;
    float css = (cs_out[k] + EPSF) / (n + (float)KCODES * EPSF) * n;
    emb_out[idx] = na / css;
}

// ---------------------------------------------------------------------------
extern "C" void kernel_launch(void* const* d_in, const int* in_sizes, int n_in,
                              void* d_out, int out_size) {
    const float* z_e  = (const float*)d_in[0];  // [N, D]
    const float* emb  = (const float*)d_in[1];  // [K, D]
    const float* cs   = (const float*)d_in[2];  // [K]
    const float* eavg = (const float*)d_in[3];  // [K, D]

    const int n_ze = in_sizes[0];               // N*D
    const int KD   = in_sizes[1];               // K*D
    const int Kk   = in_sizes[2];               // K
    const int D    = KD / Kk;
    const int N    = n_ze / D;

    float* out = (float*)d_out;
    // Tuple order: z_q_st, vq_loss, codes, new_embedding, new_cluster_size, new_embed_avg
    float* o_zq    = out;
    float* o_loss  = out + (size_t)n_ze;
    float* o_codes = o_loss + 1;
    float* o_emb   = o_codes + N;
    float* o_cs    = o_emb + KD;
    float* o_avg   = o_cs + Kk;

    int* codes_dev;
    cudaGetSymbolAddress((void**)&codes_dev, g_codes);
    __nv_bfloat16 *zh_dev, *zl_dev, *eh_dev, *el_dev;
    cudaGetSymbolAddress((void**)&zh_dev, g_zh);
    cudaGetSymbolAddress((void**)&zl_dev, g_zl);
    cudaGetSymbolAddress((void**)&eh_dev, g_eh);
    cudaGetSymbolAddress((void**)&el_dev, g_el);
    float *zsq_dev, *esq_dev;
    cudaGetSymbolAddress((void**)&zsq_dev, g_zsq);
    cudaGetSymbolAddress((void**)&esq_dev, g_esq);

    cudaFuncSetAttribute(k1_mma, cudaFuncAttributeMaxDynamicSharedMemorySize, SMEM_K1);

    k_init<<<KD / 1024, 256>>>();
    k_split_sq<<<n_ze / 1024, 256>>>(z_e, zh_dev, zl_dev, zsq_dev);
    k_split_sq<<<KD / 1024, 256>>>(emb, eh_dev, el_dev, esq_dev);
    k1_mma<<<N / 128, 256, SMEM_K1>>>(codes_dev, o_codes);
    k1_refine<<<256, 256>>>(z_e, emb, codes_dev, o_codes);
    k2_gather_scatter<<<N / 4, 256>>>(z_e, emb, codes_dev, o_zq);
    k3_cluster<<<1, Kk>>>(cs, o_cs, o_loss, 1.0f / (float)n_ze);
    k4_embed<<<Kk, D>>>(eavg, o_cs, o_avg, o_emb);
}

// round 12
// speedup vs baseline: 1.8814x; 1.0583x over previous
#include <cuda_runtime.h>
#include <cuda_bf16.h>
#include <stdint.h>

// Problem constants
#define KCODES 1024
#define DDIM   256
#define NROWS  65536
#define DECAYF 0.99f
#define ONE_MINUS_DECAY 0.01f
#define BETAF  0.25f
#define EPSF   1e-5f
#define GAPF   2e-3f      // flag threshold: covers max bf16-split dot error w/ margin

// Scratch (__device__ globals; no allocations allowed)
__device__ __align__(16) __nv_bfloat16 g_zh[NROWS * DDIM];
__device__ __align__(16) __nv_bfloat16 g_zl[NROWS * DDIM];
__device__ __align__(16) __nv_bfloat16 g_eh[KCODES * DDIM];
__device__ __align__(16) __nv_bfloat16 g_el[KCODES * DDIM];
__device__ float  g_esq[KCODES];
__device__ float  g_zsq[NROWS];
__device__ int    g_codes[NROWS];
__device__ int    g_flag_list[NROWS];
__device__ int    g_flag_cnt;
__device__ float  g_cs_batch[KCODES];
__device__ float  g_embed_sum[KCODES * DDIM];
__device__ double g_loss;
__device__ float  g_nsum;

// ---------------------------------------------------------------------------
// k_init: zero scatter buffers + counters. 256 blocks x 256 thr.
// ---------------------------------------------------------------------------
__global__ __launch_bounds__(256) void k_init() {
    int tid = threadIdx.x;
    int idx = blockIdx.x * 256 + tid;          // float4 index into embed_sum
    ((float4*)g_embed_sum)[idx] = make_float4(0.f, 0.f, 0.f, 0.f);
    if (blockIdx.x == 0) {
        ((float4*)g_cs_batch)[tid] = make_float4(0.f, 0.f, 0.f, 0.f);
        if (tid == 0) { g_loss = 0.0; g_nsum = 0.0f; g_flag_cnt = 0; }
    }
}

// ---------------------------------------------------------------------------
// k_split_sq: fp32 -> bf16 hi + bf16 lo (residual), fused fp64 row sum-of-sq.
// Half-warp per row (16 lanes x 4 float4 = 64 float4 = 256 floats). MLP=4.
// Block 256 thr = 16 rows; grid = rows/16.
// ---------------------------------------------------------------------------
__global__ __launch_bounds__(256) void k_split_sq(const float* __restrict__ src,
                                                  __nv_bfloat16* __restrict__ h,
                                                  __nv_bfloat16* __restrict__ l,
                                                  float* __restrict__ sq) {
    const int tid  = threadIdx.x;
    const int warp = tid >> 5;
    const int lane = tid & 31;
    const int half = lane & 15;
    const int row  = blockIdx.x * 16 + warp * 2 + (lane >> 4);

    const float4* srow = (const float4*)(src + (size_t)row * DDIM);
    float4 v[4];
#pragma unroll
    for (int i = 0; i < 4; i++) v[i] = srow[half + 16 * i];

    double s = 0.0;
#pragma unroll
    for (int i = 0; i < 4; i++) {
        int gidx = row * 64 + half + 16 * i;   // global float4 index
        float4 w = v[i];
        __nv_bfloat16 h0 = __float2bfloat16_rn(w.x);
        __nv_bfloat16 h1 = __float2bfloat16_rn(w.y);
        __nv_bfloat16 h2 = __float2bfloat16_rn(w.z);
        __nv_bfloat16 h3 = __float2bfloat16_rn(w.w);
        __nv_bfloat16 l0 = __float2bfloat16_rn(w.x - __bfloat162float(h0));
        __nv_bfloat16 l1 = __float2bfloat16_rn(w.y - __bfloat162float(h1));
        __nv_bfloat16 l2 = __float2bfloat16_rn(w.z - __bfloat162float(h2));
        __nv_bfloat16 l3 = __float2bfloat16_rn(w.w - __bfloat162float(h3));
        __nv_bfloat162* hp = reinterpret_cast<__nv_bfloat162*>(h) + gidx * 2;
        __nv_bfloat162* lp = reinterpret_cast<__nv_bfloat162*>(l) + gidx * 2;
        __nv_bfloat162 a; a.x = h0; a.y = h1; hp[0] = a;
        __nv_bfloat162 b; b.x = h2; b.y = h3; hp[1] = b;
        __nv_bfloat162 c; c.x = l0; c.y = l1; lp[0] = c;
        __nv_bfloat162 d; d.x = l2; d.y = l3; lp[1] = d;
        s += (double)w.x * w.x + (double)w.y * w.y
           + (double)w.z * w.z + (double)w.w * w.w;
    }
    // xor-shuffle reduce within the 16-lane half (offsets < 16 stay in group)
#pragma unroll
    for (int off = 8; off > 0; off >>= 1)
        s += __shfl_xor_sync(0xffffffffu, s, off);
    if (half == 0) sq[row] = (float)s;
}

// ---------------------------------------------------------------------------
// async-copy / mma helpers
// ---------------------------------------------------------------------------
__device__ __forceinline__ void cp_async16(uint32_t dst, const void* src) {
    asm volatile("cp.async.cg.shared.global [%0], [%1], 16;" :: "r"(dst), "l"(src));
}
__device__ __forceinline__ void cp_commit() {
    asm volatile("cp.async.commit_group;");
}
template <int N> __device__ __forceinline__ void cp_wait() {
    asm volatile("cp.async.wait_group %0;" :: "n"(N));
}
__device__ __forceinline__ void ldsm_x4(uint32_t& r0, uint32_t& r1, uint32_t& r2, uint32_t& r3,
                                        uint32_t addr) {
    asm volatile("ldmatrix.sync.aligned.m8n8.x4.shared.b16 {%0,%1,%2,%3}, [%4];"
                 : "=r"(r0), "=r"(r1), "=r"(r2), "=r"(r3) : "r"(addr));
}
__device__ __forceinline__ void mma_bf16(float* cfr, uint32_t a0, uint32_t a1, uint32_t a2,
                                         uint32_t a3, uint32_t b0, uint32_t b1) {
    asm volatile("mma.sync.aligned.m16n8k16.row.col.f32.bf16.bf16.f32 "
                 "{%0,%1,%2,%3}, {%4,%5,%6,%7}, {%8,%9}, {%0,%1,%2,%3};"
                 : "+f"(cfr[0]), "+f"(cfr[1]), "+f"(cfr[2]), "+f"(cfr[3])
                 : "r"(a0), "r"(a1), "r"(a2), "r"(a3), "r"(b0), "r"(b1));
}
__device__ __forceinline__ void red_add_v4(float* gptr, float4 v) {
    asm volatile("red.global.add.v4.f32 [%0], {%1,%2,%3,%4};"
                 :: "l"(gptr), "f"(v.x), "f"(v.y), "f"(v.z), "f"(v.w) : "memory");
}
__device__ __forceinline__ void upd(float& b, float& s, int& i, float v, int col) {
    if (v < b) { s = b; b = v; i = col; }
    else if (v < s) { s = v; }
}
__device__ __forceinline__ void merge2(float& b, float& s, int& i,
                                       float ob, float os, int oi) {
    float ns = fminf(s, os);
    if (ob < b || (ob == b && oi < i)) { ns = fminf(ns, b); b = ob; i = oi; }
    else { ns = fminf(ns, ob); }
    s = ns;
}

// ---------------------------------------------------------------------------
// Kernel 1: 3-term bf16-split GEMM via mma.sync, cp.async double-buffered,
// fused quantized-distance argmin, fused flag compaction, fused loss sum.
// Block: 128 rows x passes of 128 codes; 256 thr = 8 warps (4m x 2n); 2 CTA/SM.
// ---------------------------------------------------------------------------
#define PITCH_B   80                 // bytes per smem row (64 data + 16 pad)
#define TILE_ST   (128 * PITCH_B)    // 10240 B per tile
#define STAGE_ST  (4 * TILE_ST)      // 40960 B per stage (Ah, Al, Bh, Bl)
#define SMEM_TILES (2 * STAGE_ST)    // 81920 B
#define SMEM_K1   (SMEM_TILES + 512 + 3 * 1024)

__global__ __launch_bounds__(256, 2) void k1_mma(int* __restrict__ codes_i,
                                                 float* __restrict__ codes_f) {
    extern __shared__ char smem[];
    float* sEsq = (float*)(smem + SMEM_TILES);
    float* sFb  = (float*)(smem + SMEM_TILES + 512);
    float* sFs  = (float*)(smem + SMEM_TILES + 512 + 1024);
    int*   sFi  = (int*)  (smem + SMEM_TILES + 512 + 2048);

    const int tid  = threadIdx.x;
    const int lane = tid & 31;
    const int warp = tid >> 5;
    const int wm   = warp & 3;
    const int wn   = warp >> 2;
    const int row0 = blockIdx.x * 128;
    const uint32_t sbase = (uint32_t)__cvta_generic_to_shared(smem);

    const int rbase = wm * 32 + (lane >> 2);
    float zs[4];
#pragma unroll
    for (int r = 0; r < 4; r++) zs[r] = g_zsq[row0 + rbase + r * 8];

    float best[4], secv[4];
    int   bidx[4];
#pragma unroll
    for (int r = 0; r < 4; r++) { best[r] = 3.0e38f; secv[r] = 3.0e38f; bidx[r] = 0x7fffffff; }

    auto issue = [&](int kc, int st, int n0) {
        const int k0 = kc * 32;
#pragma unroll
        for (int it = 0; it < 8; it++) {
            int tile = it >> 1;
            int rr   = ((tid >> 2) + it * 64) & 127;
            int sub  = tid & 3;
            const __nv_bfloat16* gp;
            if      (tile == 0) gp = g_zh + (size_t)(row0 + rr) * DDIM;
            else if (tile == 1) gp = g_zl + (size_t)(row0 + rr) * DDIM;
            else if (tile == 2) gp = g_eh + (size_t)(n0 + rr) * DDIM;
            else                gp = g_el + (size_t)(n0 + rr) * DDIM;
            uint32_t dst = sbase + st * STAGE_ST + tile * TILE_ST + rr * PITCH_B + sub * 16;
            cp_async16(dst, gp + k0 + sub * 8);
        }
        cp_commit();
    };

    for (int n0 = 0; n0 < KCODES; n0 += 128) {
        __syncthreads();
        if (tid < 128) sEsq[tid] = g_esq[n0 + tid];

        float acc[2][8][4];
#pragma unroll
        for (int mt = 0; mt < 2; mt++)
#pragma unroll
            for (int nt = 0; nt < 8; nt++)
#pragma unroll
                for (int q = 0; q < 4; q++) acc[mt][nt][q] = 0.0f;

        issue(0, 0, n0);

        for (int kc = 0; kc < 8; kc++) {
            if (kc < 7) issue(kc + 1, (kc + 1) & 1, n0);
            if (kc < 7) cp_wait<1>(); else cp_wait<0>();
            __syncthreads();

            const int st = kc & 1;
            const uint32_t bAh = sbase + st * STAGE_ST;
            const uint32_t bAl = bAh + TILE_ST;
            const uint32_t bBh = bAh + 2 * TILE_ST;
            const uint32_t bBl = bAh + 3 * TILE_ST;

#pragma unroll
            for (int ks = 0; ks < 2; ks++) {
                const uint32_t koff = ks * 32;
                uint32_t Ah[2][4], Al[2][4];
#pragma unroll
                for (int mt = 0; mt < 2; mt++) {
                    uint32_t off = (uint32_t)(wm * 32 + mt * 16 + (lane & 15)) * PITCH_B
                                 + koff + ((lane >> 4) & 1) * 16;
                    ldsm_x4(Ah[mt][0], Ah[mt][1], Ah[mt][2], Ah[mt][3], bAh + off);
                    ldsm_x4(Al[mt][0], Al[mt][1], Al[mt][2], Al[mt][3], bAl + off);
                }
                // B: x4 ldmatrix covers 2 n-tiles (lanes grouped by 8)
                const int g  = lane >> 3;
                const int rb = lane & 7;
#pragma unroll
                for (int ntp = 0; ntp < 4; ntp++) {
                    uint32_t nrow = (uint32_t)(wn * 64 + (ntp * 2 + (g >> 1)) * 8 + rb);
                    uint32_t off  = nrow * PITCH_B + koff + (g & 1) * 16;
                    uint32_t Bh0, Bh1, Bh2, Bh3, Bl0, Bl1, Bl2, Bl3;
                    ldsm_x4(Bh0, Bh1, Bh2, Bh3, bBh + off);
                    ldsm_x4(Bl0, Bl1, Bl2, Bl3, bBl + off);
                    const int nt0 = ntp * 2, nt1 = nt0 + 1;
#pragma unroll
                    for (int mt = 0; mt < 2; mt++) {
                        mma_bf16(acc[mt][nt0], Ah[mt][0], Ah[mt][1], Ah[mt][2], Ah[mt][3], Bh0, Bh1);
                        mma_bf16(acc[mt][nt0], Al[mt][0], Al[mt][1], Al[mt][2], Al[mt][3], Bh0, Bh1);
                        mma_bf16(acc[mt][nt0], Ah[mt][0], Ah[mt][1], Ah[mt][2], Ah[mt][3], Bl0, Bl1);
                        mma_bf16(acc[mt][nt1], Ah[mt][0], Ah[mt][1], Ah[mt][2], Ah[mt][3], Bh2, Bh3);
                        mma_bf16(acc[mt][nt1], Al[mt][0], Al[mt][1], Al[mt][2], Al[mt][3], Bh2, Bh3);
                        mma_bf16(acc[mt][nt1], Ah[mt][0], Ah[mt][1], Ah[mt][2], Ah[mt][3], Bl2, Bl3);
                    }
                }
            }
            __syncthreads();
        }

        // Epilogue: quantized distance + top-2 fold (cols ascending per thread)
        const int qc = lane & 3;
#pragma unroll
        for (int nt = 0; nt < 8; nt++) {
#pragma unroll
            for (int cp = 0; cp < 2; cp++) {
                int cl  = wn * 64 + nt * 8 + qc * 2 + cp;
                float esq = sEsq[cl];
                int col = n0 + cl;
                float v;
                v = __fadd_rn(__fadd_rn(zs[0], -2.0f * acc[0][nt][cp]),     esq);
                upd(best[0], secv[0], bidx[0], v, col);
                v = __fadd_rn(__fadd_rn(zs[1], -2.0f * acc[0][nt][2 + cp]), esq);
                upd(best[1], secv[1], bidx[1], v, col);
                v = __fadd_rn(__fadd_rn(zs[2], -2.0f * acc[1][nt][cp]),     esq);
                upd(best[2], secv[2], bidx[2], v, col);
                v = __fadd_rn(__fadd_rn(zs[3], -2.0f * acc[1][nt][2 + cp]), esq);
                upd(best[3], secv[3], bidx[3], v, col);
            }
        }
    }

    // Quad reduction (lanes within group-of-4 share rows, hold different cols)
#pragma unroll
    for (int off = 1; off <= 2; off <<= 1) {
#pragma unroll
        for (int r = 0; r < 4; r++) {
            float ob = __shfl_xor_sync(0xffffffffu, best[r], off);
            float os = __shfl_xor_sync(0xffffffffu, secv[r], off);
            int   oi = __shfl_xor_sync(0xffffffffu, bidx[r], off);
            merge2(best[r], secv[r], bidx[r], ob, os, oi);
        }
    }
    if ((lane & 3) == 0) {
#pragma unroll
        for (int r = 0; r < 4; r++) {
            int rl = wm * 32 + (lane >> 2) + r * 8;
            sFb[rl * 2 + wn] = best[r];
            sFs[rl * 2 + wn] = secv[r];
            sFi[rl * 2 + wn] = bidx[r];
        }
    }
    __syncthreads();
    float* sLoss = sFs;                       // reuse after final merge reads
    if (tid < 128) {
        float b = sFb[tid * 2], s = sFs[tid * 2];
        int   i = sFi[tid * 2];
        merge2(b, s, i, sFb[tid * 2 + 1], sFs[tid * 2 + 1], sFi[tid * 2 + 1]);
        int row = row0 + tid;
        codes_i[row] = i;
        codes_f[row] = (float)i;
        if (s - b <= GAPF) {                  // near-tie flag compaction
            int p = atomicAdd(&g_flag_cnt, 1);
            g_flag_list[p] = row;
        }
        sFb[tid] = b;                         // stage for loss reduction
    }
    __syncthreads();
    if (tid < 64) sLoss[tid] = sFb[tid] + sFb[tid + 64];
    __syncthreads();
    if (tid < 32) {
        float s = sLoss[tid] + sLoss[tid + 32];
#pragma unroll
        for (int off = 16; off > 0; off >>= 1)
            s += __shfl_down_sync(0xffffffffu, s, off);
        if (tid == 0) atomicAdd(&g_loss, (double)s);
    }
}

// ---------------------------------------------------------------------------
// k1_refine: exact fp64-dot recompute for flagged rows (fixed small grid).
// ---------------------------------------------------------------------------
__global__ __launch_bounds__(256) void k1_refine(const float* __restrict__ z,
                                                 const float* __restrict__ emb,
                                                 int* __restrict__ codes_i,
                                                 float* __restrict__ codes_f) {
    __shared__ float zrow[DDIM];
    __shared__ float sv[256];
    __shared__ int   si[256];
    int t = threadIdx.x;
    int cnt = g_flag_cnt;
    for (int fi = blockIdx.x; fi < cnt; fi += gridDim.x) {
        int row = g_flag_list[fi];
        zrow[t] = z[(size_t)row * DDIM + t];
        __syncthreads();

        float zsq = g_zsq[row];
        float bv = 3.0e38f;
        int   bi = 0x7fffffff;
        for (int c = t; c < KCODES; c += 256) {
            const float4* e4 = (const float4*)(emb + (size_t)c * DDIM);
            const float4* z4 = (const float4*)zrow;
            double dot = 0.0;
#pragma unroll 8
            for (int q = 0; q < DDIM / 4; q++) {
                float4 ev = e4[q];
                float4 zv = z4[q];
                dot += (double)zv.x * ev.x + (double)zv.y * ev.y
                     + (double)zv.z * ev.z + (double)zv.w * ev.w;
            }
            float m = (float)(2.0 * dot);        // exactly rounded RN(2*dot)
            float u = __fadd_rn(zsq, -m);
            float v = __fadd_rn(u, g_esq[c]);
            if (v < bv) { bv = v; bi = c; }      // ascending c -> lowest index on ties
        }
        sv[t] = bv; si[t] = bi;
        __syncthreads();
        for (int s = 128; s > 0; s >>= 1) {
            if (t < s) {
                float v = sv[t + s]; int id = si[t + s];
                if (v < sv[t] || (v == sv[t] && id < si[t])) { sv[t] = v; si[t] = id; }
            }
            __syncthreads();
        }
        if (t == 0) {
            codes_i[row] = si[0];
            codes_f[row] = (float)si[0];
        }
        __syncthreads();
    }
}

// ---------------------------------------------------------------------------
// Kernel 2: warp-per-row gather z_q + vectorized scatter (red.v4.f32).
// 256 thr = 8 warps = 8 rows; each lane 2 float4s. grid N/8.
// ---------------------------------------------------------------------------
__global__ __launch_bounds__(256) void k2_gather_scatter(const float* __restrict__ z,
                                                         const float* __restrict__ emb,
                                                         const int* __restrict__ codes,
                                                         float* __restrict__ zq_out) {
    const int tid  = threadIdx.x;
    const int warp = tid >> 5;
    const int lane = tid & 31;
    const int row  = blockIdx.x * 8 + warp;
    const int c    = codes[row];

    const float4* zr = (const float4*)(z   + (size_t)row * DDIM);
    const float4* er = (const float4*)(emb + (size_t)c   * DDIM);
    float4 z0 = zr[lane];
    float4 z1 = zr[lane + 32];
    float4 e0 = er[lane];
    float4 e1 = er[lane + 32];
    float4* out = (float4*)(zq_out + (size_t)row * DDIM);
    out[lane]      = e0;
    out[lane + 32] = e1;
    float* es = g_embed_sum + (size_t)c * DDIM;
    red_add_v4(es + lane * 4,        z0);
    red_add_v4(es + (lane + 32) * 4, z1);
    if (lane == 0) atomicAdd(&g_cs_batch[c], 1.0f);
}

// ---------------------------------------------------------------------------
// Kernel 3: new_cluster_size + n-sum + vq_loss (single block)
// ---------------------------------------------------------------------------
__global__ __launch_bounds__(KCODES) void k3_cluster(const float* __restrict__ cs_in,
                                                     float* __restrict__ cs_out,
                                                     float* __restrict__ loss_out,
                                                     float inv_nd) {
    __shared__ float red[KCODES];
    int t = threadIdx.x;
    float ncs = cs_in[t] * DECAYF + g_cs_batch[t] * ONE_MINUS_DECAY;
    cs_out[t] = ncs;
    red[t] = ncs;
    __syncthreads();
    for (int s = KCODES / 2; s > 0; s >>= 1) {
        if (t < s) red[t] += red[t + s];
        __syncthreads();
    }
    if (t == 0) {
        g_nsum = red[0];
        loss_out[0] = BETAF * (float)(g_loss * (double)inv_nd);
    }
}

// ---------------------------------------------------------------------------
// Kernel 4: new_embed_avg + smoothed normalize -> new_embedding
// ---------------------------------------------------------------------------
__global__ __launch_bounds__(DDIM) void k4_embed(const float* __restrict__ avg_in,
                                                 const float* __restrict__ cs_out,
                                                 float* __restrict__ avg_out,
                                                 float* __restrict__ emb_out) {
    int k = blockIdx.x;
    int t = threadIdx.x;
    size_t idx = (size_t)k * DDIM + t;
    float na = avg_in[idx] * DECAYF + g_embed_sum[idx] * ONE_MINUS_DECAY;
    avg_out[idx] = na;
    float n = g_nsum;
    float css = (cs_out[k] + EPSF) / (n + (float)KCODES * EPSF) * n;
    emb_out[idx] = na / css;
}

// ---------------------------------------------------------------------------
extern "C" void kernel_launch(void* const* d_in, const int* in_sizes, int n_in,
                              void* d_out, int out_size) {
    const float* z_e  = (const float*)d_in[0];  // [N, D]
    const float* emb  = (const float*)d_in[1];  // [K, D]
    const float* cs   = (const float*)d_in[2];  // [K]
    const float* eavg = (const float*)d_in[3];  // [K, D]

    const int n_ze = in_sizes[0];               // N*D
    const int KD   = in_sizes[1];               // K*D
    const int Kk   = in_sizes[2];               // K
    const int D    = KD / Kk;
    const int N    = n_ze / D;

    float* out = (float*)d_out;
    // Tuple order: z_q_st, vq_loss, codes, new_embedding, new_cluster_size, new_embed_avg
    float* o_zq    = out;
    float* o_loss  = out + (size_t)n_ze;
    float* o_codes = o_loss + 1;
    float* o_emb   = o_codes + N;
    float* o_cs    = o_emb + KD;
    float* o_avg   = o_cs + Kk;

    int* codes_dev;
    cudaGetSymbolAddress((void**)&codes_dev, g_codes);
    __nv_bfloat16 *zh_dev, *zl_dev, *eh_dev, *el_dev;
    cudaGetSymbolAddress((void**)&zh_dev, g_zh);
    cudaGetSymbolAddress((void**)&zl_dev, g_zl);
    cudaGetSymbolAddress((void**)&eh_dev, g_eh);
    cudaGetSymbolAddress((void**)&el_dev, g_el);
    float *zsq_dev, *esq_dev;
    cudaGetSymbolAddress((void**)&zsq_dev, g_zsq);
    cudaGetSymbolAddress((void**)&esq_dev, g_esq);

    cudaFuncSetAttribute(k1_mma, cudaFuncAttributeMaxDynamicSharedMemorySize, SMEM_K1);

    k_init<<<KD / 1024, 256>>>();
    k_split_sq<<<N / 16, 256>>>(z_e, zh_dev, zl_dev, zsq_dev);
    k_split_sq<<<Kk / 16, 256>>>(emb, eh_dev, el_dev, esq_dev);
    k1_mma<<<N / 128, 256, SMEM_K1>>>(codes_dev, o_codes);
    k1_refine<<<256, 256>>>(z_e, emb, codes_dev, o_codes);
    k2_gather_scatter<<<N / 8, 256>>>(z_e, emb, codes_dev, o_zq);
    k3_cluster<<<1, Kk>>>(cs, o_cs, o_loss, 1.0f / (float)n_ze);
    k4_embed<<<Kk, D>>>(eavg, o_cs, o_avg, o_emb);
}